// round 10
// baseline (speedup 1.0000x reference)
#include <cuda_runtime.h>
#include <cuda_fp16.h>
#include <mma.h>
#include <cstdint>

using namespace nvcuda;

#define NN 50000
#define NP 50048        // padded rows: 391 * 128
#define NE 800000
#define RREL 8
#define NSTAGE 4

// ---------------- static device scratch ----------------
__device__ int    g_cnt[NN * RREL];
__device__ float  g_inv[NN * RREL];
__device__ int    g_deg[NN];
__device__ int    g_off[NN + 1];
__device__ int    g_cur[NN];
__device__ int    g_eidx[NE];
__device__ float  g_xW[(size_t)NP * 2048];   // 410 MB; layer-2 reuses
__device__ float  g_agg[NP * 256];           // root GEMM output (base for aggregation)
__device__ float  g_h1[NN * 256];
__device__ float  g_H[2 * (size_t)NP * 256]; // Hs | Hd
__device__ __half g_wt[1015808];             // fp16 weights

#define OFF_W1 0
#define OFF_R1 524288
#define OFF_W2 589824
#define OFF_R2 851968
#define OFF_M1 884736   // mlpW1 (512x256): Hs rows 0:128, Hd 128:256, Wt 256:512

#define CP16(dst, src) \
    asm volatile("cp.async.cg.shared.global [%0], [%1], 16;" :: "r"(dst), "l"(src))
#define CP_COMMIT() asm volatile("cp.async.commit_group;" ::: "memory")
template <int N>
__device__ __forceinline__ void cp_wait() {
    asm volatile("cp.async.wait_group %0;" :: "n"(N) : "memory");
}
__device__ __forceinline__ uint32_t sptr(const void* p) {
    return (uint32_t)__cvta_generic_to_shared(p);
}

// ================= wmma fp16 GEMM: reg-double-buffer A + cp.async B =================
// C[M, 128-blocks] = A[M,K](fp32) @ B[K,N](fp16); block tile 128x128, warp 64x32.
#define ALD 24      // halves
#define BLD 136     // halves
__global__ void __launch_bounds__(256, 2) twmma_kernel(const float* __restrict__ A,
                                                       const __half* __restrict__ B,
                                                       float* __restrict__ C,
                                                       int M, int K, int lda, int ldb, int ldc,
                                                       long sB, long sC) {
    extern __shared__ __half hsm[];
    __half* sA = hsm;                       // [2][128*ALD]
    __half* sB_ = hsm + 2 * 128 * ALD;      // [NSTAGE][16*BLD]

    B += (long)blockIdx.z * sB;
    C += (long)blockIdx.z * sC;
    int bm = blockIdx.x * 128;
    int bn = blockIdx.y * 128;

    int tid = threadIdx.x;
    int w = tid >> 5;
    int wm = w & 1;
    int wn = w >> 1;

    wmma::fragment<wmma::accumulator, 16, 16, 16, float> acc[4][2];
#pragma unroll
    for (int i = 0; i < 4; i++)
#pragma unroll
        for (int j = 0; j < 2; j++) wmma::fill_fragment(acc[i][j], 0.f);

    int ar = tid >> 1, ah = (tid & 1) * 8;
    bool ok = (bm + ar) < M;
    const float* aB = A + (size_t)(bm + ar) * lda + ah;
    float4 ra0, ra1;

    int brow = tid >> 4, bc8 = tid & 15;    // one 16B chunk (8 halves) per thread
    const __half* bBase = B + (size_t)brow * ldb + bn + bc8 * 8;

#define LOADA(kt) do { \
        ra0 = ok ? __ldg((const float4*)(aB + (kt)))     : make_float4(0.f, 0.f, 0.f, 0.f); \
        ra1 = ok ? __ldg((const float4*)(aB + (kt) + 4)) : make_float4(0.f, 0.f, 0.f, 0.f); \
    } while (0)
#define STOREA(buf) do { \
        __half* s = sA + (buf) * 128 * ALD + ar * ALD + ah; \
        ((half2*)s)[0] = __floats2half2_rn(ra0.x, ra0.y); \
        ((half2*)s)[1] = __floats2half2_rn(ra0.z, ra0.w); \
        ((half2*)s)[2] = __floats2half2_rn(ra1.x, ra1.y); \
        ((half2*)s)[3] = __floats2half2_rn(ra1.z, ra1.w); \
    } while (0)
#define ISSUEB(stage, kt) do { \
        uint32_t d = sptr(sB_ + (stage) * 16 * BLD + brow * BLD + bc8 * 8); \
        CP16(d, bBase + (size_t)(kt) * ldb); \
    } while (0)

    int nk = K >> 4;
#pragma unroll
    for (int s = 0; s < NSTAGE - 1; s++) {
        if (s < nk) ISSUEB(s, s << 4);
        CP_COMMIT();
    }
    LOADA(0);
    STOREA(0);

    for (int i = 0; i < nk; i++) {
        if (i + 1 < nk) LOADA((i + 1) << 4);
        cp_wait<NSTAGE - 2>();
        __syncthreads();
        if (i + NSTAGE - 1 < nk) ISSUEB((i + NSTAGE - 1) % NSTAGE, (i + NSTAGE - 1) << 4);
        CP_COMMIT();

        __half* sa = sA + (i & 1) * 128 * ALD;
        __half* sb = sB_ + (i % NSTAGE) * 16 * BLD;
        wmma::fragment<wmma::matrix_a, 16, 16, 16, __half, wmma::row_major> af[4];
        wmma::fragment<wmma::matrix_b, 16, 16, 16, __half, wmma::row_major> bf[2];
#pragma unroll
        for (int x = 0; x < 4; x++)
            wmma::load_matrix_sync(af[x], sa + (wm * 64 + x * 16) * ALD, ALD);
#pragma unroll
        for (int y = 0; y < 2; y++)
            wmma::load_matrix_sync(bf[y], sb + wn * 32 + y * 16, BLD);
#pragma unroll
        for (int x = 0; x < 4; x++)
#pragma unroll
            for (int y = 0; y < 2; y++)
                wmma::mma_sync(acc[x][y], af[x], bf[y], acc[x][y]);

        if (i + 1 < nk) STOREA((i + 1) & 1);
    }

#pragma unroll
    for (int i = 0; i < 4; i++)
#pragma unroll
        for (int j = 0; j < 2; j++) {
            size_t off = (size_t)(bm + wm * 64 + i * 16) * ldc + bn + wn * 32 + j * 16;
            wmma::store_matrix_sync(C + off, acc[i][j], ldc, wmma::mem_row_major);
        }
#undef LOADA
#undef STOREA
#undef ISSUEB
}

// ================= fused edge MLP, fp16 =================
#define EALD 24
#define EBLD 264
__global__ void __launch_bounds__(256, 2) edge_fused_kernel(const int* __restrict__ srcv,
                                                            const int* __restrict__ dstv,
                                                            const float* __restrict__ etext,
                                                            const __half* __restrict__ Wt,
                                                            const float* __restrict__ b1v,
                                                            const float* __restrict__ w2v,
                                                            const float* __restrict__ b2v,
                                                            const float* __restrict__ Hs,
                                                            const float* __restrict__ Hd,
                                                            float* __restrict__ logits) {
    extern __shared__ __half hsm[];
    __half* sA = hsm;                       // [2][64*EALD]
    __half* sB = hsm + 2 * 64 * EALD;       // [NSTAGE][16*EBLD]
    float*  sC = (float*)hsm;               // [64][256] fp32 overlay

    int tid = threadIdx.x;
    int w = tid >> 5, lane = tid & 31;
    int bm = blockIdx.x * 64;

    wmma::fragment<wmma::accumulator, 16, 16, 16, float> acc[4][2];
#pragma unroll
    for (int i = 0; i < 4; i++)
#pragma unroll
        for (int j = 0; j < 2; j++) wmma::fill_fragment(acc[i][j], 0.f);

    int ar = tid >> 2, aq = (tid & 3) * 4;
    const float* aB = etext + (size_t)(bm + ar) * 256 + aq;
    float4 ra;

    int brow = tid >> 4, bc16 = (tid & 15) * 16;   // 16 halves (2 chunks) per thread
    const __half* bBase = Wt + (size_t)brow * 256 + bc16;

#define ELOADA(kt)  do { ra = __ldg((const float4*)(aB + (kt))); } while (0)
#define ESTOREA(buf) do { \
        __half* s = sA + (buf) * 64 * EALD + ar * EALD + aq; \
        ((half2*)s)[0] = __floats2half2_rn(ra.x, ra.y); \
        ((half2*)s)[1] = __floats2half2_rn(ra.z, ra.w); \
    } while (0)
#define EISSUEB(stage, kt) do { \
        uint32_t d = sptr(sB + (stage) * 16 * EBLD + brow * EBLD + bc16); \
        const __half* sgp = bBase + (size_t)(kt) * 256; \
        CP16(d, sgp); CP16(d + 16, sgp + 8); \
    } while (0)

    const int nk = 16;
#pragma unroll
    for (int s = 0; s < NSTAGE - 1; s++) {
        EISSUEB(s, s << 4);
        CP_COMMIT();
    }
    ELOADA(0);
    ESTOREA(0);

    for (int i = 0; i < nk; i++) {
        if (i + 1 < nk) ELOADA((i + 1) << 4);
        cp_wait<NSTAGE - 2>();
        __syncthreads();
        if (i + NSTAGE - 1 < nk) EISSUEB((i + NSTAGE - 1) % NSTAGE, (i + NSTAGE - 1) << 4);
        CP_COMMIT();

        __half* sa = sA + (i & 1) * 64 * EALD;
        __half* sb = sB + (i % NSTAGE) * 16 * EBLD;
        wmma::fragment<wmma::matrix_a, 16, 16, 16, __half, wmma::row_major> af[4];
        wmma::fragment<wmma::matrix_b, 16, 16, 16, __half, wmma::row_major> bf[2];
#pragma unroll
        for (int x = 0; x < 4; x++)
            wmma::load_matrix_sync(af[x], sa + (x * 16) * EALD, EALD);
#pragma unroll
        for (int y = 0; y < 2; y++)
            wmma::load_matrix_sync(bf[y], sb + w * 32 + y * 16, EBLD);
#pragma unroll
        for (int x = 0; x < 4; x++)
#pragma unroll
            for (int y = 0; y < 2; y++)
                wmma::mma_sync(acc[x][y], af[x], bf[y], acc[x][y]);

        if (i + 1 < nk) ESTOREA((i + 1) & 1);
    }

    cp_wait<0>();
    __syncthreads();
#pragma unroll
    for (int i = 0; i < 4; i++)
#pragma unroll
        for (int j = 0; j < 2; j++)
            wmma::store_matrix_sync(sC + (i * 16) * 256 + w * 32 + j * 16, acc[i][j],
                                    256, wmma::mem_row_major);
    __syncthreads();

    int c0 = lane * 8;
    float4 b1a = __ldg((const float4*)(b1v + c0));
    float4 b1b = __ldg((const float4*)(b1v + c0 + 4));
    float4 w2a = __ldg((const float4*)(w2v + c0));
    float4 w2b = __ldg((const float4*)(w2v + c0 + 4));
    float beta = __ldg(b2v);

#pragma unroll
    for (int ei = 0; ei < 8; ei++) {
        int el = w * 8 + ei;
        int e = bm + el;
        int s = __ldg(srcv + e), d = __ldg(dstv + e);
        float4 ca = *(float4*)(sC + el * 256 + c0);
        float4 cb = *(float4*)(sC + el * 256 + c0 + 4);
        float4 hsa = __ldg((const float4*)(Hs + (size_t)s * 256 + c0));
        float4 hsb = __ldg((const float4*)(Hs + (size_t)s * 256 + c0 + 4));
        float4 hda = __ldg((const float4*)(Hd + (size_t)d * 256 + c0));
        float4 hdb = __ldg((const float4*)(Hd + (size_t)d * 256 + c0 + 4));
        float p = 0.f, h;
        h = fmaxf(ca.x + hsa.x + hda.x + b1a.x, 0.f); p = fmaf(h, w2a.x, p);
        h = fmaxf(ca.y + hsa.y + hda.y + b1a.y, 0.f); p = fmaf(h, w2a.y, p);
        h = fmaxf(ca.z + hsa.z + hda.z + b1a.z, 0.f); p = fmaf(h, w2a.z, p);
        h = fmaxf(ca.w + hsa.w + hda.w + b1a.w, 0.f); p = fmaf(h, w2a.w, p);
        h = fmaxf(cb.x + hsb.x + hdb.x + b1b.x, 0.f); p = fmaf(h, w2b.x, p);
        h = fmaxf(cb.y + hsb.y + hdb.y + b1b.y, 0.f); p = fmaf(h, w2b.y, p);
        h = fmaxf(cb.z + hsb.z + hdb.z + b1b.z, 0.f); p = fmaf(h, w2b.z, p);
        h = fmaxf(cb.w + hsb.w + hdb.w + b1b.w, 0.f); p = fmaf(h, w2b.w, p);
#pragma unroll
        for (int off = 16; off > 0; off >>= 1)
            p += __shfl_down_sync(0xffffffffu, p, off);
        if (lane == 0) logits[e] = p + beta;
    }
#undef ELOADA
#undef ESTOREA
#undef EISSUEB
}

// ================= CSR build (by dst) =================
__global__ void zeroi_kernel(int* p, int n) {
    int i = blockIdx.x * blockDim.x + threadIdx.x;
    if (i < n) p[i] = 0;
}
__global__ void count_kernel(const int* __restrict__ dstv, const int* __restrict__ etype) {
    int e = blockIdx.x * blockDim.x + threadIdx.x;
    if (e < NE) atomicAdd(&g_cnt[dstv[e] * RREL + etype[e]], 1);
}
__global__ void inv_deg_kernel() {
    int d = blockIdx.x * blockDim.x + threadIdx.x;
    if (d >= NN) return;
    int tot = 0;
#pragma unroll
    for (int r = 0; r < RREL; r++) {
        int c = g_cnt[d * RREL + r];
        tot += c;
        g_inv[d * RREL + r] = c > 0 ? 1.0f / (float)c : 0.0f;
    }
    g_deg[d] = tot;
}
__global__ void scan_kernel() {
    __shared__ int s[1024];
    __shared__ int carry;
    int tid = threadIdx.x;
    if (tid == 0) carry = 0;
    __syncthreads();
    for (int base = 0; base < NN; base += 1024) {
        int v = (base + tid < NN) ? g_deg[base + tid] : 0;
        s[tid] = v;
        __syncthreads();
        for (int o = 1; o < 1024; o <<= 1) {
            int x = (tid >= o) ? s[tid - o] : 0;
            __syncthreads();
            s[tid] += x;
            __syncthreads();
        }
        if (base + tid < NN) g_off[base + tid] = carry + s[tid] - v;
        __syncthreads();
        if (tid == 0) carry += s[1023];
        __syncthreads();
    }
    if (tid == 0) g_off[NN] = carry;
}
__global__ void fill_kernel(const int* __restrict__ srcv, const int* __restrict__ dstv,
                            const int* __restrict__ etype) {
    int e = blockIdx.x * blockDim.x + threadIdx.x;
    if (e >= NE) return;
    int d = dstv[e];
    int pos = g_off[d] + atomicAdd(&g_cur[d], 1);
    g_eidx[pos] = (srcv[e] << 3) | etype[e];
}

// ================= CSR aggregation: h[d] = relu(root[d] + sum + bias) =================
template <int D>
__global__ void __launch_bounds__(256) agg_kernel(const float* __restrict__ xW,
                                                  const float* __restrict__ rootb,
                                                  const float* __restrict__ bias,
                                                  float* __restrict__ out) {
    constexpr int TPD = D / 4;
    int d = blockIdx.x * (256 / TPD) + threadIdx.x / TPD;
    int c = threadIdx.x % TPD;
    if (d >= NN) return;
    int beg = __ldg(g_off + d), end = __ldg(g_off + d + 1);
    float4 acc = make_float4(0.f, 0.f, 0.f, 0.f);
    int j = beg;
    for (; j + 1 < end; j += 2) {
        int pk0 = __ldg(g_eidx + j), pk1 = __ldg(g_eidx + j + 1);
        float w0 = __ldg(g_inv + d * RREL + (pk0 & 7));
        float w1 = __ldg(g_inv + d * RREL + (pk1 & 7));
        float4 v0 = __ldg((const float4*)(xW + (size_t)pk0 * D) + c);
        float4 v1 = __ldg((const float4*)(xW + (size_t)pk1 * D) + c);
        acc.x = fmaf(w0, v0.x, acc.x); acc.y = fmaf(w0, v0.y, acc.y);
        acc.z = fmaf(w0, v0.z, acc.z); acc.w = fmaf(w0, v0.w, acc.w);
        acc.x = fmaf(w1, v1.x, acc.x); acc.y = fmaf(w1, v1.y, acc.y);
        acc.z = fmaf(w1, v1.z, acc.z); acc.w = fmaf(w1, v1.w, acc.w);
    }
    if (j < end) {
        int pk = __ldg(g_eidx + j);
        float w = __ldg(g_inv + d * RREL + (pk & 7));
        float4 v = __ldg((const float4*)(xW + (size_t)pk * D) + c);
        acc.x = fmaf(w, v.x, acc.x); acc.y = fmaf(w, v.y, acc.y);
        acc.z = fmaf(w, v.z, acc.z); acc.w = fmaf(w, v.w, acc.w);
    }
    float4 base = __ldg((const float4*)(rootb + (size_t)d * D) + c);
    float4 b = __ldg((const float4*)bias + c);
    float4 o;
    o.x = fmaxf(acc.x + base.x + b.x, 0.f);
    o.y = fmaxf(acc.y + base.y + b.y, 0.f);
    o.z = fmaxf(acc.z + base.z + b.z, 0.f);
    o.w = fmaxf(acc.w + base.w + b.w, 0.f);
    *((float4*)(out + (size_t)d * D) + c) = o;
}

// ================= utility =================
__global__ void half_copy_kernel(const float4* __restrict__ src, __half* __restrict__ dst, int n4) {
    int i = blockIdx.x * blockDim.x + threadIdx.x;
    if (i < n4) {
        float4 v = src[i];
        __half* d = dst + (size_t)i * 4;
        ((half2*)d)[0] = __floats2half2_rn(v.x, v.y);
        ((half2*)d)[1] = __floats2half2_rn(v.z, v.w);
    }
}

// ================= launch =================
extern "C" void kernel_launch(void* const* d_in, const int* in_sizes, int n_in,
                              void* d_out, int out_size) {
    const int*   edge_index = (const int*)d_in[0];
    const int*   etype      = (const int*)d_in[1];
    const float* etext      = (const float*)d_in[2];
    const float* node_emb   = (const float*)d_in[3];
    const float* W1         = (const float*)d_in[4];
    const float* root1      = (const float*)d_in[5];
    const float* b1         = (const float*)d_in[6];
    const float* W2         = (const float*)d_in[7];
    const float* root2      = (const float*)d_in[8];
    const float* b2         = (const float*)d_in[9];
    const float* mlpW1      = (const float*)d_in[10];
    const float* mlpb1      = (const float*)d_in[11];
    const float* mlpW2      = (const float*)d_in[12];
    const float* mlpb2      = (const float*)d_in[13];

    const int* srcv = edge_index;
    const int* dstv = edge_index + NE;
    float* logits = (float*)d_out;
    float* h2     = (float*)d_out + NE;

    void* p;
    cudaGetSymbolAddress(&p, g_cnt); int*    cntp = (int*)p;
    cudaGetSymbolAddress(&p, g_cur); int*    curp = (int*)p;
    cudaGetSymbolAddress(&p, g_xW);  float*  xW   = (float*)p;
    cudaGetSymbolAddress(&p, g_agg); float*  agg  = (float*)p;
    cudaGetSymbolAddress(&p, g_h1);  float*  h1   = (float*)p;
    cudaGetSymbolAddress(&p, g_H);   float*  H    = (float*)p;
    cudaGetSymbolAddress(&p, g_wt);  __half* wt   = (__half*)p;

    const int GSMEM = (2 * 128 * ALD + NSTAGE * 16 * BLD) * 2;      // 29696
    const int ESMEM = 64 * 256 * 4;                                  // 65536 (>= staging 39936)
    cudaFuncSetAttribute(twmma_kernel, cudaFuncAttributeMaxDynamicSharedMemorySize, GSMEM);
    cudaFuncSetAttribute(edge_fused_kernel, cudaFuncAttributeMaxDynamicSharedMemorySize, ESMEM);

    // weight conversion to fp16
    half_copy_kernel<<<512, 256>>>((const float4*)W1, wt + OFF_W1, 524288 / 4);
    half_copy_kernel<<<64, 256>>>((const float4*)root1, wt + OFF_R1, 65536 / 4);
    half_copy_kernel<<<256, 256>>>((const float4*)W2, wt + OFF_W2, 262144 / 4);
    half_copy_kernel<<<32, 256>>>((const float4*)root2, wt + OFF_R2, 32768 / 4);
    half_copy_kernel<<<128, 256>>>((const float4*)mlpW1, wt + OFF_M1, 131072 / 4);

    // CSR build
    zeroi_kernel<<<(NN * RREL + 255) / 256, 256>>>(cntp, NN * RREL);
    zeroi_kernel<<<(NN + 255) / 256, 256>>>(curp, NN);
    count_kernel<<<(NE + 255) / 256, 256>>>(dstv, etype);
    inv_deg_kernel<<<(NN + 255) / 256, 256>>>();
    scan_kernel<<<1, 1024>>>();
    fill_kernel<<<(NE + 255) / 256, 256>>>(srcv, dstv, etype);

    const int MB = NP / 128;  // 391

    // ---- layer 1 ----
    twmma_kernel<<<dim3(MB, 2, 8), 256, GSMEM>>>(node_emb, wt + OFF_W1, xW,
                                                 NN, 256, 256, 256, 2048, 65536L, 256L);
    twmma_kernel<<<dim3(MB, 2, 1), 256, GSMEM>>>(node_emb, wt + OFF_R1, agg,
                                                 NN, 256, 256, 256, 256, 0L, 0L);
    agg_kernel<256><<<(NN + 3) / 4, 256>>>(xW, agg, b1, h1);

    // ---- layer 2 ----
    twmma_kernel<<<dim3(MB, 1, 8), 256, GSMEM>>>(h1, wt + OFF_W2, xW,
                                                 NN, 256, 256, 128, 1024, 32768L, 128L);
    twmma_kernel<<<dim3(MB, 1, 1), 256, GSMEM>>>(h1, wt + OFF_R2, agg,
                                                 NN, 256, 256, 128, 128, 0L, 0L);
    agg_kernel<128><<<(NN + 7) / 8, 256>>>(xW, agg, b2, h2);

    // ---- edge MLP: Hs|Hd in one z=2 launch, then fused edge kernel ----
    twmma_kernel<<<dim3(MB, 2, 2), 256, GSMEM>>>(h2, wt + OFF_M1, H,
                                                 NN, 128, 128, 256, 256,
                                                 32768L, (long)NP * 256);
    edge_fused_kernel<<<NE / 64, 256, ESMEM>>>(srcv, dstv, etext, wt + OFF_M1 + 65536,
                                               mlpb1, mlpW2, mlpb2,
                                               H, H + (size_t)NP * 256, logits);
}

// round 11
// speedup vs baseline: 1.0009x; 1.0009x over previous
#include <cuda_runtime.h>
#include <cuda_fp16.h>
#include <mma.h>
#include <cstdint>

using namespace nvcuda;

#define NN 50000
#define NP 50048        // padded rows: 391 * 128
#define NE 800000
#define RREL 8
#define NSTAGE 4

// ---------------- static device scratch ----------------
__device__ int    g_cnt[NN * RREL];
__device__ float  g_inv[NN * RREL];
__device__ int    g_deg[NN];
__device__ int    g_off[NN + 1];
__device__ int    g_cur[NN];
__device__ int    g_eidx[NE];
__device__ float  g_xW[(size_t)NP * 2048];   // 410 MB; layer-2 reuses
__device__ float  g_agg[NP * 256];           // root GEMM output (base for aggregation)
__device__ float  g_h1[NN * 256];
__device__ float  g_H[2 * (size_t)NP * 256]; // Hs | Hd
__device__ __half g_wt[1015808];             // fp16 weights

#define OFF_W1 0
#define OFF_R1 524288
#define OFF_W2 589824
#define OFF_R2 851968
#define OFF_M1 884736   // mlpW1 (512x256): Hs rows 0:128, Hd 128:256, Wt 256:512

#define CP16(dst, src) \
    asm volatile("cp.async.cg.shared.global [%0], [%1], 16;" :: "r"(dst), "l"(src))
#define CP_COMMIT() asm volatile("cp.async.commit_group;" ::: "memory")
template <int N>
__device__ __forceinline__ void cp_wait() {
    asm volatile("cp.async.wait_group %0;" :: "n"(N) : "memory");
}
__device__ __forceinline__ uint32_t sptr(const void* p) {
    return (uint32_t)__cvta_generic_to_shared(p);
}

// ================= wmma fp16 GEMM: reg-double-buffer A + cp.async B =================
// C[M, 128-blocks] = A[M,K](fp32) @ B[K,N](fp16); block tile 128x128, warp 64x32.
#define ALD 24      // halves
#define BLD 136     // halves
__global__ void __launch_bounds__(256, 2) twmma_kernel(const float* __restrict__ A,
                                                       const __half* __restrict__ B,
                                                       float* __restrict__ C,
                                                       int M, int K, int lda, int ldb, int ldc,
                                                       long sB, long sC) {
    extern __shared__ __half hsm[];
    __half* sA = hsm;                       // [2][128*ALD]
    __half* sB_ = hsm + 2 * 128 * ALD;      // [NSTAGE][16*BLD]

    B += (long)blockIdx.z * sB;
    C += (long)blockIdx.z * sC;
    int bm = blockIdx.x * 128;
    int bn = blockIdx.y * 128;

    int tid = threadIdx.x;
    int w = tid >> 5;
    int wm = w & 1;
    int wn = w >> 1;

    wmma::fragment<wmma::accumulator, 16, 16, 16, float> acc[4][2];
#pragma unroll
    for (int i = 0; i < 4; i++)
#pragma unroll
        for (int j = 0; j < 2; j++) wmma::fill_fragment(acc[i][j], 0.f);

    int ar = tid >> 1, ah = (tid & 1) * 8;
    bool ok = (bm + ar) < M;
    const float* aB = A + (size_t)(bm + ar) * lda + ah;
    float4 ra0, ra1;

    int brow = tid >> 4, bc8 = tid & 15;    // one 16B chunk (8 halves) per thread
    const __half* bBase = B + (size_t)brow * ldb + bn + bc8 * 8;

#define LOADA(kt) do { \
        ra0 = ok ? __ldg((const float4*)(aB + (kt)))     : make_float4(0.f, 0.f, 0.f, 0.f); \
        ra1 = ok ? __ldg((const float4*)(aB + (kt) + 4)) : make_float4(0.f, 0.f, 0.f, 0.f); \
    } while (0)
#define STOREA(buf) do { \
        __half* s = sA + (buf) * 128 * ALD + ar * ALD + ah; \
        ((half2*)s)[0] = __floats2half2_rn(ra0.x, ra0.y); \
        ((half2*)s)[1] = __floats2half2_rn(ra0.z, ra0.w); \
        ((half2*)s)[2] = __floats2half2_rn(ra1.x, ra1.y); \
        ((half2*)s)[3] = __floats2half2_rn(ra1.z, ra1.w); \
    } while (0)
#define ISSUEB(stage, kt) do { \
        uint32_t d = sptr(sB_ + (stage) * 16 * BLD + brow * BLD + bc8 * 8); \
        CP16(d, bBase + (size_t)(kt) * ldb); \
    } while (0)

    int nk = K >> 4;
#pragma unroll
    for (int s = 0; s < NSTAGE - 1; s++) {
        if (s < nk) ISSUEB(s, s << 4);
        CP_COMMIT();
    }
    LOADA(0);
    STOREA(0);

    for (int i = 0; i < nk; i++) {
        if (i + 1 < nk) LOADA((i + 1) << 4);
        cp_wait<NSTAGE - 2>();
        __syncthreads();
        if (i + NSTAGE - 1 < nk) ISSUEB((i + NSTAGE - 1) % NSTAGE, (i + NSTAGE - 1) << 4);
        CP_COMMIT();

        __half* sa = sA + (i & 1) * 128 * ALD;
        __half* sb = sB_ + (i % NSTAGE) * 16 * BLD;
        wmma::fragment<wmma::matrix_a, 16, 16, 16, __half, wmma::row_major> af[4];
        wmma::fragment<wmma::matrix_b, 16, 16, 16, __half, wmma::row_major> bf[2];
#pragma unroll
        for (int x = 0; x < 4; x++)
            wmma::load_matrix_sync(af[x], sa + (wm * 64 + x * 16) * ALD, ALD);
#pragma unroll
        for (int y = 0; y < 2; y++)
            wmma::load_matrix_sync(bf[y], sb + wn * 32 + y * 16, BLD);
#pragma unroll
        for (int x = 0; x < 4; x++)
#pragma unroll
            for (int y = 0; y < 2; y++)
                wmma::mma_sync(acc[x][y], af[x], bf[y], acc[x][y]);

        if (i + 1 < nk) STOREA((i + 1) & 1);
    }

#pragma unroll
    for (int i = 0; i < 4; i++)
#pragma unroll
        for (int j = 0; j < 2; j++) {
            size_t off = (size_t)(bm + wm * 64 + i * 16) * ldc + bn + wn * 32 + j * 16;
            wmma::store_matrix_sync(C + off, acc[i][j], ldc, wmma::mem_row_major);
        }
#undef LOADA
#undef STOREA
#undef ISSUEB
}

// ================= fused edge MLP, fp16 =================
#define EALD 24
#define EBLD 264
__global__ void __launch_bounds__(256, 2) edge_fused_kernel(const int* __restrict__ srcv,
                                                            const int* __restrict__ dstv,
                                                            const float* __restrict__ etext,
                                                            const __half* __restrict__ Wt,
                                                            const float* __restrict__ b1v,
                                                            const float* __restrict__ w2v,
                                                            const float* __restrict__ b2v,
                                                            const float* __restrict__ Hs,
                                                            const float* __restrict__ Hd,
                                                            float* __restrict__ logits) {
    extern __shared__ __half hsm[];
    __half* sA = hsm;                       // [2][64*EALD]
    __half* sB = hsm + 2 * 64 * EALD;       // [NSTAGE][16*EBLD]
    float*  sC = (float*)hsm;               // [64][256] fp32 overlay

    int tid = threadIdx.x;
    int w = tid >> 5, lane = tid & 31;
    int bm = blockIdx.x * 64;

    wmma::fragment<wmma::accumulator, 16, 16, 16, float> acc[4][2];
#pragma unroll
    for (int i = 0; i < 4; i++)
#pragma unroll
        for (int j = 0; j < 2; j++) wmma::fill_fragment(acc[i][j], 0.f);

    int ar = tid >> 2, aq = (tid & 3) * 4;
    const float* aB = etext + (size_t)(bm + ar) * 256 + aq;
    float4 ra;

    int brow = tid >> 4, bc16 = (tid & 15) * 16;   // 16 halves (2 chunks) per thread
    const __half* bBase = Wt + (size_t)brow * 256 + bc16;

#define ELOADA(kt)  do { ra = __ldg((const float4*)(aB + (kt))); } while (0)
#define ESTOREA(buf) do { \
        __half* s = sA + (buf) * 64 * EALD + ar * EALD + aq; \
        ((half2*)s)[0] = __floats2half2_rn(ra.x, ra.y); \
        ((half2*)s)[1] = __floats2half2_rn(ra.z, ra.w); \
    } while (0)
#define EISSUEB(stage, kt) do { \
        uint32_t d = sptr(sB + (stage) * 16 * EBLD + brow * EBLD + bc16); \
        const __half* sgp = bBase + (size_t)(kt) * 256; \
        CP16(d, sgp); CP16(d + 16, sgp + 8); \
    } while (0)

    const int nk = 16;
#pragma unroll
    for (int s = 0; s < NSTAGE - 1; s++) {
        EISSUEB(s, s << 4);
        CP_COMMIT();
    }
    ELOADA(0);
    ESTOREA(0);

    for (int i = 0; i < nk; i++) {
        if (i + 1 < nk) ELOADA((i + 1) << 4);
        cp_wait<NSTAGE - 2>();
        __syncthreads();
        if (i + NSTAGE - 1 < nk) EISSUEB((i + NSTAGE - 1) % NSTAGE, (i + NSTAGE - 1) << 4);
        CP_COMMIT();

        __half* sa = sA + (i & 1) * 64 * EALD;
        __half* sb = sB + (i % NSTAGE) * 16 * EBLD;
        wmma::fragment<wmma::matrix_a, 16, 16, 16, __half, wmma::row_major> af[4];
        wmma::fragment<wmma::matrix_b, 16, 16, 16, __half, wmma::row_major> bf[2];
#pragma unroll
        for (int x = 0; x < 4; x++)
            wmma::load_matrix_sync(af[x], sa + (x * 16) * EALD, EALD);
#pragma unroll
        for (int y = 0; y < 2; y++)
            wmma::load_matrix_sync(bf[y], sb + w * 32 + y * 16, EBLD);
#pragma unroll
        for (int x = 0; x < 4; x++)
#pragma unroll
            for (int y = 0; y < 2; y++)
                wmma::mma_sync(acc[x][y], af[x], bf[y], acc[x][y]);

        if (i + 1 < nk) ESTOREA((i + 1) & 1);
    }

    cp_wait<0>();
    __syncthreads();
#pragma unroll
    for (int i = 0; i < 4; i++)
#pragma unroll
        for (int j = 0; j < 2; j++)
            wmma::store_matrix_sync(sC + (i * 16) * 256 + w * 32 + j * 16, acc[i][j],
                                    256, wmma::mem_row_major);
    __syncthreads();

    int c0 = lane * 8;
    float4 b1a = __ldg((const float4*)(b1v + c0));
    float4 b1b = __ldg((const float4*)(b1v + c0 + 4));
    float4 w2a = __ldg((const float4*)(w2v + c0));
    float4 w2b = __ldg((const float4*)(w2v + c0 + 4));
    float beta = __ldg(b2v);

#pragma unroll
    for (int ei = 0; ei < 8; ei++) {
        int el = w * 8 + ei;
        int e = bm + el;
        int s = __ldg(srcv + e), d = __ldg(dstv + e);
        float4 ca = *(float4*)(sC + el * 256 + c0);
        float4 cb = *(float4*)(sC + el * 256 + c0 + 4);
        float4 hsa = __ldg((const float4*)(Hs + (size_t)s * 256 + c0));
        float4 hsb = __ldg((const float4*)(Hs + (size_t)s * 256 + c0 + 4));
        float4 hda = __ldg((const float4*)(Hd + (size_t)d * 256 + c0));
        float4 hdb = __ldg((const float4*)(Hd + (size_t)d * 256 + c0 + 4));
        float p = 0.f, h;
        h = fmaxf(ca.x + hsa.x + hda.x + b1a.x, 0.f); p = fmaf(h, w2a.x, p);
        h = fmaxf(ca.y + hsa.y + hda.y + b1a.y, 0.f); p = fmaf(h, w2a.y, p);
        h = fmaxf(ca.z + hsa.z + hda.z + b1a.z, 0.f); p = fmaf(h, w2a.z, p);
        h = fmaxf(ca.w + hsa.w + hda.w + b1a.w, 0.f); p = fmaf(h, w2a.w, p);
        h = fmaxf(cb.x + hsb.x + hdb.x + b1b.x, 0.f); p = fmaf(h, w2b.x, p);
        h = fmaxf(cb.y + hsb.y + hdb.y + b1b.y, 0.f); p = fmaf(h, w2b.y, p);
        h = fmaxf(cb.z + hsb.z + hdb.z + b1b.z, 0.f); p = fmaf(h, w2b.z, p);
        h = fmaxf(cb.w + hsb.w + hdb.w + b1b.w, 0.f); p = fmaf(h, w2b.w, p);
#pragma unroll
        for (int off = 16; off > 0; off >>= 1)
            p += __shfl_down_sync(0xffffffffu, p, off);
        if (lane == 0) logits[e] = p + beta;
    }
#undef ELOADA
#undef ESTOREA
#undef EISSUEB
}

// ================= CSR build (by dst) =================
__global__ void zeroi_kernel(int* p, int n) {
    int i = blockIdx.x * blockDim.x + threadIdx.x;
    if (i < n) p[i] = 0;
}
__global__ void count_kernel(const int* __restrict__ dstv, const int* __restrict__ etype) {
    int e = blockIdx.x * blockDim.x + threadIdx.x;
    if (e < NE) atomicAdd(&g_cnt[dstv[e] * RREL + etype[e]], 1);
}
__global__ void inv_deg_kernel() {
    int d = blockIdx.x * blockDim.x + threadIdx.x;
    if (d >= NN) return;
    int tot = 0;
#pragma unroll
    for (int r = 0; r < RREL; r++) {
        int c = g_cnt[d * RREL + r];
        tot += c;
        g_inv[d * RREL + r] = c > 0 ? 1.0f / (float)c : 0.0f;
    }
    g_deg[d] = tot;
}
__global__ void scan_kernel() {
    __shared__ int s[1024];
    __shared__ int carry;
    int tid = threadIdx.x;
    if (tid == 0) carry = 0;
    __syncthreads();
    for (int base = 0; base < NN; base += 1024) {
        int v = (base + tid < NN) ? g_deg[base + tid] : 0;
        s[tid] = v;
        __syncthreads();
        for (int o = 1; o < 1024; o <<= 1) {
            int x = (tid >= o) ? s[tid - o] : 0;
            __syncthreads();
            s[tid] += x;
            __syncthreads();
        }
        if (base + tid < NN) g_off[base + tid] = carry + s[tid] - v;
        __syncthreads();
        if (tid == 0) carry += s[1023];
        __syncthreads();
    }
    if (tid == 0) g_off[NN] = carry;
}
__global__ void fill_kernel(const int* __restrict__ srcv, const int* __restrict__ dstv,
                            const int* __restrict__ etype) {
    int e = blockIdx.x * blockDim.x + threadIdx.x;
    if (e >= NE) return;
    int d = dstv[e];
    int pos = g_off[d] + atomicAdd(&g_cur[d], 1);
    g_eidx[pos] = (srcv[e] << 3) | etype[e];
}

// ================= CSR aggregation: h[d] = relu(root[d] + sum + bias) =================
template <int D>
__global__ void __launch_bounds__(256) agg_kernel(const float* __restrict__ xW,
                                                  const float* __restrict__ rootb,
                                                  const float* __restrict__ bias,
                                                  float* __restrict__ out) {
    constexpr int TPD = D / 4;
    int d = blockIdx.x * (256 / TPD) + threadIdx.x / TPD;
    int c = threadIdx.x % TPD;
    if (d >= NN) return;
    int beg = __ldg(g_off + d), end = __ldg(g_off + d + 1);
    float4 acc = make_float4(0.f, 0.f, 0.f, 0.f);
    int j = beg;
    for (; j + 1 < end; j += 2) {
        int pk0 = __ldg(g_eidx + j), pk1 = __ldg(g_eidx + j + 1);
        float w0 = __ldg(g_inv + d * RREL + (pk0 & 7));
        float w1 = __ldg(g_inv + d * RREL + (pk1 & 7));
        float4 v0 = __ldg((const float4*)(xW + (size_t)pk0 * D) + c);
        float4 v1 = __ldg((const float4*)(xW + (size_t)pk1 * D) + c);
        acc.x = fmaf(w0, v0.x, acc.x); acc.y = fmaf(w0, v0.y, acc.y);
        acc.z = fmaf(w0, v0.z, acc.z); acc.w = fmaf(w0, v0.w, acc.w);
        acc.x = fmaf(w1, v1.x, acc.x); acc.y = fmaf(w1, v1.y, acc.y);
        acc.z = fmaf(w1, v1.z, acc.z); acc.w = fmaf(w1, v1.w, acc.w);
    }
    if (j < end) {
        int pk = __ldg(g_eidx + j);
        float w = __ldg(g_inv + d * RREL + (pk & 7));
        float4 v = __ldg((const float4*)(xW + (size_t)pk * D) + c);
        acc.x = fmaf(w, v.x, acc.x); acc.y = fmaf(w, v.y, acc.y);
        acc.z = fmaf(w, v.z, acc.z); acc.w = fmaf(w, v.w, acc.w);
    }
    float4 base = __ldg((const float4*)(rootb + (size_t)d * D) + c);
    float4 b = __ldg((const float4*)bias + c);
    float4 o;
    o.x = fmaxf(acc.x + base.x + b.x, 0.f);
    o.y = fmaxf(acc.y + base.y + b.y, 0.f);
    o.z = fmaxf(acc.z + base.z + b.z, 0.f);
    o.w = fmaxf(acc.w + base.w + b.w, 0.f);
    *((float4*)(out + (size_t)d * D) + c) = o;
}

// ================= utility =================
__global__ void half_copy_kernel(const float4* __restrict__ src, __half* __restrict__ dst, int n4) {
    int i = blockIdx.x * blockDim.x + threadIdx.x;
    if (i < n4) {
        float4 v = src[i];
        __half* d = dst + (size_t)i * 4;
        ((half2*)d)[0] = __floats2half2_rn(v.x, v.y);
        ((half2*)d)[1] = __floats2half2_rn(v.z, v.w);
    }
}

// ================= launch =================
extern "C" void kernel_launch(void* const* d_in, const int* in_sizes, int n_in,
                              void* d_out, int out_size) {
    const int*   edge_index = (const int*)d_in[0];
    const int*   etype      = (const int*)d_in[1];
    const float* etext      = (const float*)d_in[2];
    const float* node_emb   = (const float*)d_in[3];
    const float* W1         = (const float*)d_in[4];
    const float* root1      = (const float*)d_in[5];
    const float* b1         = (const float*)d_in[6];
    const float* W2         = (const float*)d_in[7];
    const float* root2      = (const float*)d_in[8];
    const float* b2         = (const float*)d_in[9];
    const float* mlpW1      = (const float*)d_in[10];
    const float* mlpb1      = (const float*)d_in[11];
    const float* mlpW2      = (const float*)d_in[12];
    const float* mlpb2      = (const float*)d_in[13];

    const int* srcv = edge_index;
    const int* dstv = edge_index + NE;
    float* logits = (float*)d_out;
    float* h2     = (float*)d_out + NE;

    void* p;
    cudaGetSymbolAddress(&p, g_cnt); int*    cntp = (int*)p;
    cudaGetSymbolAddress(&p, g_cur); int*    curp = (int*)p;
    cudaGetSymbolAddress(&p, g_xW);  float*  xW   = (float*)p;
    cudaGetSymbolAddress(&p, g_agg); float*  agg  = (float*)p;
    cudaGetSymbolAddress(&p, g_h1);  float*  h1   = (float*)p;
    cudaGetSymbolAddress(&p, g_H);   float*  H    = (float*)p;
    cudaGetSymbolAddress(&p, g_wt);  __half* wt   = (__half*)p;

    const int GSMEM = (2 * 128 * ALD + NSTAGE * 16 * BLD) * 2;      // 29696
    const int ESMEM = 64 * 256 * 4;                                  // 65536 (>= staging 39936)
    cudaFuncSetAttribute(twmma_kernel, cudaFuncAttributeMaxDynamicSharedMemorySize, GSMEM);
    cudaFuncSetAttribute(edge_fused_kernel, cudaFuncAttributeMaxDynamicSharedMemorySize, ESMEM);

    // weight conversion to fp16
    half_copy_kernel<<<512, 256>>>((const float4*)W1, wt + OFF_W1, 524288 / 4);
    half_copy_kernel<<<64, 256>>>((const float4*)root1, wt + OFF_R1, 65536 / 4);
    half_copy_kernel<<<256, 256>>>((const float4*)W2, wt + OFF_W2, 262144 / 4);
    half_copy_kernel<<<32, 256>>>((const float4*)root2, wt + OFF_R2, 32768 / 4);
    half_copy_kernel<<<128, 256>>>((const float4*)mlpW1, wt + OFF_M1, 131072 / 4);

    // CSR build
    zeroi_kernel<<<(NN * RREL + 255) / 256, 256>>>(cntp, NN * RREL);
    zeroi_kernel<<<(NN + 255) / 256, 256>>>(curp, NN);
    count_kernel<<<(NE + 255) / 256, 256>>>(dstv, etype);
    inv_deg_kernel<<<(NN + 255) / 256, 256>>>();
    scan_kernel<<<1, 1024>>>();
    fill_kernel<<<(NE + 255) / 256, 256>>>(srcv, dstv, etype);

    const int MB = NP / 128;  // 391

    // ---- layer 1 ----
    twmma_kernel<<<dim3(MB, 2, 8), 256, GSMEM>>>(node_emb, wt + OFF_W1, xW,
                                                 NN, 256, 256, 256, 2048, 65536L, 256L);
    twmma_kernel<<<dim3(MB, 2, 1), 256, GSMEM>>>(node_emb, wt + OFF_R1, agg,
                                                 NN, 256, 256, 256, 256, 0L, 0L);
    agg_kernel<256><<<(NN + 3) / 4, 256>>>(xW, agg, b1, h1);

    // ---- layer 2 ----
    twmma_kernel<<<dim3(MB, 1, 8), 256, GSMEM>>>(h1, wt + OFF_W2, xW,
                                                 NN, 256, 256, 128, 1024, 32768L, 128L);
    twmma_kernel<<<dim3(MB, 1, 1), 256, GSMEM>>>(h1, wt + OFF_R2, agg,
                                                 NN, 256, 256, 128, 128, 0L, 0L);
    agg_kernel<128><<<(NN + 7) / 8, 256>>>(xW, agg, b2, h2);

    // ---- edge MLP: Hs|Hd in one z=2 launch, then fused edge kernel ----
    twmma_kernel<<<dim3(MB, 2, 2), 256, GSMEM>>>(h2, wt + OFF_M1, H,
                                                 NN, 128, 128, 256, 256,
                                                 32768L, (long)NP * 256);
    edge_fused_kernel<<<NE / 64, 256, ESMEM>>>(srcv, dstv, etext, wt + OFF_M1 + 65536,
                                               mlpb1, mlpW2, mlpb2,
                                               H, H + (size_t)NP * 256, logits);
}

// round 12
// speedup vs baseline: 1.0661x; 1.0651x over previous
#include <cuda_runtime.h>
#include <cuda_fp16.h>
#include <mma.h>
#include <cstdint>

using namespace nvcuda;

#define NN 50000
#define NP 50048        // padded rows: 391 * 128
#define NE 800000
#define RREL 8
#define NSTAGE 4

// ---------------- static device scratch ----------------
__device__ int    g_cnt[NN * RREL];
__device__ float  g_inv[NN * RREL];
__device__ int    g_deg[NN];
__device__ int    g_off[NN + 1];
__device__ int    g_cur[NN];
__device__ int    g_eidx[NE];
__device__ __half g_xWh[(size_t)NP * 2048];   // 205 MB; layer-2 reuses
__device__ __half g_aggh[NP * 256];           // root GEMM output (half)
__device__ __half g_h1h[NP * 256];
__device__ __half g_h2h[NP * 128];
__device__ __half g_Hh[2 * (size_t)NP * 256]; // Hs | Hd (half)
__device__ __half g_wt[1015808];              // fp16 weights

#define OFF_W1 0
#define OFF_R1 524288
#define OFF_W2 589824
#define OFF_R2 851968
#define OFF_M1 884736   // mlpW1 (512x256): Hs rows 0:128, Hd 128:256, Wt 256:512

#define CP16(dst, src) \
    asm volatile("cp.async.cg.shared.global [%0], [%1], 16;" :: "r"(dst), "l"(src))
#define CP_COMMIT() asm volatile("cp.async.commit_group;" ::: "memory")
template <int N>
__device__ __forceinline__ void cp_wait() {
    asm volatile("cp.async.wait_group %0;" :: "n"(N) : "memory");
}
__device__ __forceinline__ uint32_t sptr(const void* p) {
    return (uint32_t)__cvta_generic_to_shared(p);
}

// ================= wmma fp16 GEMM: templated A type, half C output =================
// C[M, 128-blocks](fp16) = A[M,K] @ B[K,N](fp16); block tile 128x128, warp 64x32.
#define ALD 24      // halves
#define BLD 136     // halves
#define SLD 132     // floats, C epilogue tile ld
template <typename TA>
__global__ void __launch_bounds__(256, 2) twmma_kernel(const TA* __restrict__ A,
                                                       const __half* __restrict__ B,
                                                       __half* __restrict__ C,
                                                       int M, int K, int lda, int ldb, int ldc,
                                                       long sB, long sC) {
    constexpr bool AFLOAT = sizeof(TA) == 4;
    extern __shared__ __half hsm[];
    __half* sA = hsm;                       // [2][128*ALD]
    __half* sB_ = hsm + 2 * 128 * ALD;      // [NSTAGE][16*BLD]
    float*  sCf = (float*)hsm;              // [128][SLD] epilogue overlay

    B += (long)blockIdx.z * sB;
    C += (long)blockIdx.z * sC;
    int bm = blockIdx.x * 128;
    int bn = blockIdx.y * 128;

    int tid = threadIdx.x;
    int w = tid >> 5;
    int wm = w & 1;
    int wn = w >> 1;

    wmma::fragment<wmma::accumulator, 16, 16, 16, float> acc[4][2];
#pragma unroll
    for (int i = 0; i < 4; i++)
#pragma unroll
        for (int j = 0; j < 2; j++) wmma::fill_fragment(acc[i][j], 0.f);

    int ar = tid >> 1, ah = (tid & 1) * 8;
    bool ok = (bm + ar) < M;
    const TA* aB = A + (size_t)(bm + ar) * lda + ah;
    float4 ra0, ra1;      // used when AFLOAT
    uint4  rh;            // used when !AFLOAT

    int brow = tid >> 4, bc8 = tid & 15;    // one 16B chunk (8 halves) per thread
    const __half* bBase = B + (size_t)brow * ldb + bn + bc8 * 8;

#define LOADA(kt) do { \
        if constexpr (AFLOAT) { \
            ra0 = ok ? __ldg((const float4*)(aB + (kt)))     : make_float4(0.f, 0.f, 0.f, 0.f); \
            ra1 = ok ? __ldg((const float4*)(aB + (kt) + 4)) : make_float4(0.f, 0.f, 0.f, 0.f); \
        } else { \
            rh = ok ? __ldg((const uint4*)(aB + (kt))) : make_uint4(0u, 0u, 0u, 0u); \
        } \
    } while (0)
#define STOREA(buf) do { \
        __half* s = sA + (buf) * 128 * ALD + ar * ALD + ah; \
        if constexpr (AFLOAT) { \
            ((half2*)s)[0] = __floats2half2_rn(ra0.x, ra0.y); \
            ((half2*)s)[1] = __floats2half2_rn(ra0.z, ra0.w); \
            ((half2*)s)[2] = __floats2half2_rn(ra1.x, ra1.y); \
            ((half2*)s)[3] = __floats2half2_rn(ra1.z, ra1.w); \
        } else { \
            *(uint4*)s = rh; \
        } \
    } while (0)
#define ISSUEB(stage, kt) do { \
        uint32_t d = sptr(sB_ + (stage) * 16 * BLD + brow * BLD + bc8 * 8); \
        CP16(d, bBase + (size_t)(kt) * ldb); \
    } while (0)

    int nk = K >> 4;
#pragma unroll
    for (int s = 0; s < NSTAGE - 1; s++) {
        if (s < nk) ISSUEB(s, s << 4);
        CP_COMMIT();
    }
    LOADA(0);
    STOREA(0);

    for (int i = 0; i < nk; i++) {
        if (i + 1 < nk) LOADA((i + 1) << 4);
        cp_wait<NSTAGE - 2>();
        __syncthreads();
        if (i + NSTAGE - 1 < nk) ISSUEB((i + NSTAGE - 1) % NSTAGE, (i + NSTAGE - 1) << 4);
        CP_COMMIT();

        __half* sa = sA + (i & 1) * 128 * ALD;
        __half* sb = sB_ + (i % NSTAGE) * 16 * BLD;
        wmma::fragment<wmma::matrix_a, 16, 16, 16, __half, wmma::row_major> af[4];
        wmma::fragment<wmma::matrix_b, 16, 16, 16, __half, wmma::row_major> bf[2];
#pragma unroll
        for (int x = 0; x < 4; x++)
            wmma::load_matrix_sync(af[x], sa + (wm * 64 + x * 16) * ALD, ALD);
#pragma unroll
        for (int y = 0; y < 2; y++)
            wmma::load_matrix_sync(bf[y], sb + wn * 32 + y * 16, BLD);
#pragma unroll
        for (int x = 0; x < 4; x++)
#pragma unroll
            for (int y = 0; y < 2; y++)
                wmma::mma_sync(acc[x][y], af[x], bf[y], acc[x][y]);

        if (i + 1 < nk) STOREA((i + 1) & 1);
    }

    // ---- epilogue: acc -> SMEM fp32 tile -> global half ----
    cp_wait<0>();
    __syncthreads();   // staging dead from here
#pragma unroll
    for (int i = 0; i < 4; i++)
#pragma unroll
        for (int j = 0; j < 2; j++)
            wmma::store_matrix_sync(sCf + (wm * 64 + i * 16) * SLD + wn * 32 + j * 16,
                                    acc[i][j], SLD, wmma::mem_row_major);
    __syncthreads();

    {
        int r = tid >> 1;
        int ch = (tid & 1) * 64;
        if (bm + r < M) {
            __half* gp = C + (size_t)(bm + r) * ldc + bn + ch;
            const float* sp = sCf + r * SLD + ch;
#pragma unroll
            for (int q = 0; q < 8; q++) {
                float4 v0 = *(const float4*)(sp + q * 8);
                float4 v1 = *(const float4*)(sp + q * 8 + 4);
                uint4 o;
                half2* op = (half2*)&o;
                op[0] = __floats2half2_rn(v0.x, v0.y);
                op[1] = __floats2half2_rn(v0.z, v0.w);
                op[2] = __floats2half2_rn(v1.x, v1.y);
                op[3] = __floats2half2_rn(v1.z, v1.w);
                *(uint4*)(gp + q * 8) = o;
            }
        }
    }
#undef LOADA
#undef STOREA
#undef ISSUEB
}

// ================= fused edge MLP, fp16 (Hs/Hd in half) =================
#define EALD 24
#define EBLD 264
__global__ void __launch_bounds__(256, 2) edge_fused_kernel(const int* __restrict__ srcv,
                                                            const int* __restrict__ dstv,
                                                            const float* __restrict__ etext,
                                                            const __half* __restrict__ Wt,
                                                            const float* __restrict__ b1v,
                                                            const float* __restrict__ w2v,
                                                            const float* __restrict__ b2v,
                                                            const __half* __restrict__ Hs,
                                                            const __half* __restrict__ Hd,
                                                            float* __restrict__ logits) {
    extern __shared__ __half hsm[];
    __half* sA = hsm;                       // [2][64*EALD]
    __half* sB = hsm + 2 * 64 * EALD;       // [NSTAGE][16*EBLD]
    float*  sC = (float*)hsm;               // [64][256] fp32 overlay

    int tid = threadIdx.x;
    int w = tid >> 5, lane = tid & 31;
    int bm = blockIdx.x * 64;

    wmma::fragment<wmma::accumulator, 16, 16, 16, float> acc[4][2];
#pragma unroll
    for (int i = 0; i < 4; i++)
#pragma unroll
        for (int j = 0; j < 2; j++) wmma::fill_fragment(acc[i][j], 0.f);

    int ar = tid >> 2, aq = (tid & 3) * 4;
    const float* aB = etext + (size_t)(bm + ar) * 256 + aq;
    float4 ra;

    int brow = tid >> 4, bc16 = (tid & 15) * 16;
    const __half* bBase = Wt + (size_t)brow * 256 + bc16;

#define ELOADA(kt)  do { ra = __ldg((const float4*)(aB + (kt))); } while (0)
#define ESTOREA(buf) do { \
        __half* s = sA + (buf) * 64 * EALD + ar * EALD + aq; \
        ((half2*)s)[0] = __floats2half2_rn(ra.x, ra.y); \
        ((half2*)s)[1] = __floats2half2_rn(ra.z, ra.w); \
    } while (0)
#define EISSUEB(stage, kt) do { \
        uint32_t d = sptr(sB + (stage) * 16 * EBLD + brow * EBLD + bc16); \
        const __half* sgp = bBase + (size_t)(kt) * 256; \
        CP16(d, sgp); CP16(d + 16, sgp + 8); \
    } while (0)

    const int nk = 16;
#pragma unroll
    for (int s = 0; s < NSTAGE - 1; s++) {
        EISSUEB(s, s << 4);
        CP_COMMIT();
    }
    ELOADA(0);
    ESTOREA(0);

    for (int i = 0; i < nk; i++) {
        if (i + 1 < nk) ELOADA((i + 1) << 4);
        cp_wait<NSTAGE - 2>();
        __syncthreads();
        if (i + NSTAGE - 1 < nk) EISSUEB((i + NSTAGE - 1) % NSTAGE, (i + NSTAGE - 1) << 4);
        CP_COMMIT();

        __half* sa = sA + (i & 1) * 64 * EALD;
        __half* sb = sB + (i % NSTAGE) * 16 * EBLD;
        wmma::fragment<wmma::matrix_a, 16, 16, 16, __half, wmma::row_major> af[4];
        wmma::fragment<wmma::matrix_b, 16, 16, 16, __half, wmma::row_major> bf[2];
#pragma unroll
        for (int x = 0; x < 4; x++)
            wmma::load_matrix_sync(af[x], sa + (x * 16) * EALD, EALD);
#pragma unroll
        for (int y = 0; y < 2; y++)
            wmma::load_matrix_sync(bf[y], sb + w * 32 + y * 16, EBLD);
#pragma unroll
        for (int x = 0; x < 4; x++)
#pragma unroll
            for (int y = 0; y < 2; y++)
                wmma::mma_sync(acc[x][y], af[x], bf[y], acc[x][y]);

        if (i + 1 < nk) ESTOREA((i + 1) & 1);
    }

    cp_wait<0>();
    __syncthreads();
#pragma unroll
    for (int i = 0; i < 4; i++)
#pragma unroll
        for (int j = 0; j < 2; j++)
            wmma::store_matrix_sync(sC + (i * 16) * 256 + w * 32 + j * 16, acc[i][j],
                                    256, wmma::mem_row_major);
    __syncthreads();

    int c0 = lane * 8;
    float4 b1a = __ldg((const float4*)(b1v + c0));
    float4 b1b = __ldg((const float4*)(b1v + c0 + 4));
    float4 w2a = __ldg((const float4*)(w2v + c0));
    float4 w2b = __ldg((const float4*)(w2v + c0 + 4));
    float beta = __ldg(b2v);

#pragma unroll
    for (int ei = 0; ei < 8; ei++) {
        int el = w * 8 + ei;
        int e = bm + el;
        int s = __ldg(srcv + e), d = __ldg(dstv + e);
        float4 ca = *(float4*)(sC + el * 256 + c0);
        float4 cb = *(float4*)(sC + el * 256 + c0 + 4);
        uint4 hsv = __ldg((const uint4*)(Hs + (size_t)s * 256 + c0));
        uint4 hdv = __ldg((const uint4*)(Hd + (size_t)d * 256 + c0));
        half2* hsp = (half2*)&hsv;
        half2* hdp = (half2*)&hdv;
        float2 hs0 = __half22float2(hsp[0]), hs1 = __half22float2(hsp[1]);
        float2 hs2 = __half22float2(hsp[2]), hs3 = __half22float2(hsp[3]);
        float2 hd0 = __half22float2(hdp[0]), hd1 = __half22float2(hdp[1]);
        float2 hd2 = __half22float2(hdp[2]), hd3 = __half22float2(hdp[3]);
        float p = 0.f, h;
        h = fmaxf(ca.x + hs0.x + hd0.x + b1a.x, 0.f); p = fmaf(h, w2a.x, p);
        h = fmaxf(ca.y + hs0.y + hd0.y + b1a.y, 0.f); p = fmaf(h, w2a.y, p);
        h = fmaxf(ca.z + hs1.x + hd1.x + b1a.z, 0.f); p = fmaf(h, w2a.z, p);
        h = fmaxf(ca.w + hs1.y + hd1.y + b1a.w, 0.f); p = fmaf(h, w2a.w, p);
        h = fmaxf(cb.x + hs2.x + hd2.x + b1b.x, 0.f); p = fmaf(h, w2b.x, p);
        h = fmaxf(cb.y + hs2.y + hd2.y + b1b.y, 0.f); p = fmaf(h, w2b.y, p);
        h = fmaxf(cb.z + hs3.x + hd3.x + b1b.z, 0.f); p = fmaf(h, w2b.z, p);
        h = fmaxf(cb.w + hs3.y + hd3.y + b1b.w, 0.f); p = fmaf(h, w2b.w, p);
#pragma unroll
        for (int off = 16; off > 0; off >>= 1)
            p += __shfl_down_sync(0xffffffffu, p, off);
        if (lane == 0) logits[e] = p + beta;
    }
#undef ELOADA
#undef ESTOREA
#undef EISSUEB
}

// ================= CSR build (by dst) =================
__global__ void zeroi_kernel(int* p, int n) {
    int i = blockIdx.x * blockDim.x + threadIdx.x;
    if (i < n) p[i] = 0;
}
__global__ void count_kernel(const int* __restrict__ dstv, const int* __restrict__ etype) {
    int e = blockIdx.x * blockDim.x + threadIdx.x;
    if (e < NE) atomicAdd(&g_cnt[dstv[e] * RREL + etype[e]], 1);
}
__global__ void inv_deg_kernel() {
    int d = blockIdx.x * blockDim.x + threadIdx.x;
    if (d >= NN) return;
    int tot = 0;
#pragma unroll
    for (int r = 0; r < RREL; r++) {
        int c = g_cnt[d * RREL + r];
        tot += c;
        g_inv[d * RREL + r] = c > 0 ? 1.0f / (float)c : 0.0f;
    }
    g_deg[d] = tot;
}
__global__ void scan_kernel() {
    __shared__ int s[1024];
    __shared__ int carry;
    int tid = threadIdx.x;
    if (tid == 0) carry = 0;
    __syncthreads();
    for (int base = 0; base < NN; base += 1024) {
        int v = (base + tid < NN) ? g_deg[base + tid] : 0;
        s[tid] = v;
        __syncthreads();
        for (int o = 1; o < 1024; o <<= 1) {
            int x = (tid >= o) ? s[tid - o] : 0;
            __syncthreads();
            s[tid] += x;
            __syncthreads();
        }
        if (base + tid < NN) g_off[base + tid] = carry + s[tid] - v;
        __syncthreads();
        if (tid == 0) carry += s[1023];
        __syncthreads();
    }
    if (tid == 0) g_off[NN] = carry;
}
__global__ void fill_kernel(const int* __restrict__ srcv, const int* __restrict__ dstv,
                            const int* __restrict__ etype) {
    int e = blockIdx.x * blockDim.x + threadIdx.x;
    if (e >= NE) return;
    int d = dstv[e];
    int pos = g_off[d] + atomicAdd(&g_cur[d], 1);
    g_eidx[pos] = (srcv[e] << 3) | etype[e];
}

// ================= CSR aggregation: out = relu(root + mean-sum + bias) =================
// 8 halves per thread; fp32 accumulate; writes half (and optional fp32 copy).
template <int D, bool WF>
__global__ void __launch_bounds__(256) agg_kernel(const __half* __restrict__ xW,
                                                  const __half* __restrict__ rootb,
                                                  const float* __restrict__ bias,
                                                  __half* __restrict__ outh,
                                                  float* __restrict__ outf) {
    constexpr int TPD = D / 8;                    // 32 or 16
    int d = blockIdx.x * (256 / TPD) + threadIdx.x / TPD;
    int c = threadIdx.x % TPD;
    if (d >= NN) return;
    int beg = __ldg(g_off + d), end = __ldg(g_off + d + 1);
    float a[8] = {0.f, 0.f, 0.f, 0.f, 0.f, 0.f, 0.f, 0.f};
    for (int j = beg; j < end; j++) {
        int pk = __ldg(g_eidx + j);
        float wgt = __ldg(g_inv + d * RREL + (pk & 7));
        uint4 v = __ldg((const uint4*)(xW + (size_t)pk * D) + c);
        half2* vp = (half2*)&v;
#pragma unroll
        for (int k = 0; k < 4; k++) {
            float2 f = __half22float2(vp[k]);
            a[2 * k]     = fmaf(wgt, f.x, a[2 * k]);
            a[2 * k + 1] = fmaf(wgt, f.y, a[2 * k + 1]);
        }
    }
    uint4 bv = __ldg((const uint4*)(rootb + (size_t)d * D) + c);
    half2* bp = (half2*)&bv;
    float4 bb0 = __ldg((const float4*)(bias + c * 8));
    float4 bb1 = __ldg((const float4*)(bias + c * 8 + 4));
    float bbv[8] = {bb0.x, bb0.y, bb0.z, bb0.w, bb1.x, bb1.y, bb1.z, bb1.w};
    float o[8];
#pragma unroll
    for (int k = 0; k < 4; k++) {
        float2 f = __half22float2(bp[k]);
        o[2 * k]     = fmaxf(a[2 * k] + f.x + bbv[2 * k], 0.f);
        o[2 * k + 1] = fmaxf(a[2 * k + 1] + f.y + bbv[2 * k + 1], 0.f);
    }
    uint4 ov;
    half2* op = (half2*)&ov;
#pragma unroll
    for (int k = 0; k < 4; k++) op[k] = __floats2half2_rn(o[2 * k], o[2 * k + 1]);
    *((uint4*)(outh + (size_t)d * D) + c) = ov;
    if (WF) {
        float4* fo = (float4*)(outf + (size_t)d * D + c * 8);
        fo[0] = make_float4(o[0], o[1], o[2], o[3]);
        fo[1] = make_float4(o[4], o[5], o[6], o[7]);
    }
}

// ================= utility =================
__global__ void half_copy_kernel(const float4* __restrict__ src, __half* __restrict__ dst, int n4) {
    int i = blockIdx.x * blockDim.x + threadIdx.x;
    if (i < n4) {
        float4 v = src[i];
        __half* d = dst + (size_t)i * 4;
        ((half2*)d)[0] = __floats2half2_rn(v.x, v.y);
        ((half2*)d)[1] = __floats2half2_rn(v.z, v.w);
    }
}

// ================= launch =================
extern "C" void kernel_launch(void* const* d_in, const int* in_sizes, int n_in,
                              void* d_out, int out_size) {
    const int*   edge_index = (const int*)d_in[0];
    const int*   etype      = (const int*)d_in[1];
    const float* etext      = (const float*)d_in[2];
    const float* node_emb   = (const float*)d_in[3];
    const float* W1         = (const float*)d_in[4];
    const float* root1      = (const float*)d_in[5];
    const float* b1         = (const float*)d_in[6];
    const float* W2         = (const float*)d_in[7];
    const float* root2      = (const float*)d_in[8];
    const float* b2         = (const float*)d_in[9];
    const float* mlpW1      = (const float*)d_in[10];
    const float* mlpb1      = (const float*)d_in[11];
    const float* mlpW2      = (const float*)d_in[12];
    const float* mlpb2      = (const float*)d_in[13];

    const int* srcv = edge_index;
    const int* dstv = edge_index + NE;
    float* logits = (float*)d_out;
    float* h2out  = (float*)d_out + NE;

    void* p;
    cudaGetSymbolAddress(&p, g_cnt);  int*    cntp = (int*)p;
    cudaGetSymbolAddress(&p, g_cur);  int*    curp = (int*)p;
    cudaGetSymbolAddress(&p, g_xWh);  __half* xWh  = (__half*)p;
    cudaGetSymbolAddress(&p, g_aggh); __half* aggh = (__half*)p;
    cudaGetSymbolAddress(&p, g_h1h);  __half* h1h  = (__half*)p;
    cudaGetSymbolAddress(&p, g_h2h);  __half* h2h  = (__half*)p;
    cudaGetSymbolAddress(&p, g_Hh);   __half* Hh   = (__half*)p;
    cudaGetSymbolAddress(&p, g_wt);   __half* wt   = (__half*)p;

    const int GSMEM = 128 * SLD * 4;    // 67584 (>= staging 29696)
    const int ESMEM = 64 * 256 * 4;     // 65536 (>= staging 39936)
    cudaFuncSetAttribute(twmma_kernel<float>, cudaFuncAttributeMaxDynamicSharedMemorySize, GSMEM);
    cudaFuncSetAttribute(twmma_kernel<__half>, cudaFuncAttributeMaxDynamicSharedMemorySize, GSMEM);
    cudaFuncSetAttribute(edge_fused_kernel, cudaFuncAttributeMaxDynamicSharedMemorySize, ESMEM);

    // weight conversion to fp16
    half_copy_kernel<<<512, 256>>>((const float4*)W1, wt + OFF_W1, 524288 / 4);
    half_copy_kernel<<<64, 256>>>((const float4*)root1, wt + OFF_R1, 65536 / 4);
    half_copy_kernel<<<256, 256>>>((const float4*)W2, wt + OFF_W2, 262144 / 4);
    half_copy_kernel<<<32, 256>>>((const float4*)root2, wt + OFF_R2, 32768 / 4);
    half_copy_kernel<<<128, 256>>>((const float4*)mlpW1, wt + OFF_M1, 131072 / 4);

    // CSR build
    zeroi_kernel<<<(NN * RREL + 255) / 256, 256>>>(cntp, NN * RREL);
    zeroi_kernel<<<(NN + 255) / 256, 256>>>(curp, NN);
    count_kernel<<<(NE + 255) / 256, 256>>>(dstv, etype);
    inv_deg_kernel<<<(NN + 255) / 256, 256>>>();
    scan_kernel<<<1, 1024>>>();
    fill_kernel<<<(NE + 255) / 256, 256>>>(srcv, dstv, etype);

    const int MB = NP / 128;  // 391

    // ---- layer 1 ----
    twmma_kernel<float><<<dim3(MB, 2, 8), 256, GSMEM>>>(node_emb, wt + OFF_W1, xWh,
                                                        NN, 256, 256, 256, 2048, 65536L, 256L);
    twmma_kernel<float><<<dim3(MB, 2, 1), 256, GSMEM>>>(node_emb, wt + OFF_R1, aggh,
                                                        NN, 256, 256, 256, 256, 0L, 0L);
    agg_kernel<256, false><<<(NN + 7) / 8, 256>>>(xWh, aggh, b1, h1h, nullptr);

    // ---- layer 2 ----
    twmma_kernel<__half><<<dim3(MB, 1, 8), 256, GSMEM>>>(h1h, wt + OFF_W2, xWh,
                                                         NN, 256, 256, 128, 1024, 32768L, 128L);
    twmma_kernel<__half><<<dim3(MB, 1, 1), 256, GSMEM>>>(h1h, wt + OFF_R2, aggh,
                                                         NN, 256, 256, 128, 128, 0L, 0L);
    agg_kernel<128, true><<<(NN + 15) / 16, 256>>>(xWh, aggh, b2, h2h, h2out);

    // ---- edge MLP: Hs|Hd in one z=2 launch, then fused edge kernel ----
    twmma_kernel<__half><<<dim3(MB, 2, 2), 256, GSMEM>>>(h2h, wt + OFF_M1, Hh,
                                                         NN, 128, 128, 256, 256,
                                                         32768L, (long)NP * 256);
    edge_fused_kernel<<<NE / 64, 256, ESMEM>>>(srcv, dstv, etext, wt + OFF_M1 + 65536,
                                               mlpb1, mlpW2, mlpb2,
                                               Hh, Hh + (size_t)NP * 256, logits);
}

// round 13
// speedup vs baseline: 1.1440x; 1.0731x over previous
#include <cuda_runtime.h>
#include <cuda_fp16.h>
#include <mma.h>
#include <cstdint>

using namespace nvcuda;

#define NN 50000
#define NP 50048        // padded rows: 391 * 128
#define NE 800000
#define RREL 8
#define NSTAGE 4

// ---------------- static device scratch ----------------
__device__ int    g_cnt[NN * RREL];
__device__ float  g_inv[NN * RREL];
__device__ int    g_deg[NN];
__device__ int    g_off[NN + 1];
__device__ int    g_cur[NN];
__device__ int    g_eidx[NE];
__device__ int    g_bsum[64];
__device__ __half g_xWh[(size_t)NP * 2304];   // widened rows: 8 relations + root
__device__ __half g_xh[NN * 256];             // node_emb in fp16
__device__ __half g_h1h[NP * 256];
__device__ __half g_h2h[NP * 128];
__device__ __half g_Hh[2 * (size_t)NP * 256]; // Hs | Hd (half)
__device__ __half g_wt[1015808];              // fp16 weights

#define OFF_W1 0        // W1 [8][256][256] then root1 [256][256] (contiguous)
#define OFF_R1 524288
#define OFF_W2 589824   // W2 [8][256][128] then root2 [256][128] (contiguous)
#define OFF_R2 851968
#define OFF_M1 884736   // mlpW1 (512x256): Hs rows 0:128, Hd 128:256, Wt 256:512

#define CP16(dst, src) \
    asm volatile("cp.async.cg.shared.global [%0], [%1], 16;" :: "r"(dst), "l"(src))
#define CP_COMMIT() asm volatile("cp.async.commit_group;" ::: "memory")
template <int N>
__device__ __forceinline__ void cp_wait() {
    asm volatile("cp.async.wait_group %0;" :: "n"(N) : "memory");
}
__device__ __forceinline__ uint32_t sptr(const void* p) {
    return (uint32_t)__cvta_generic_to_shared(p);
}

// ================= wmma fp16 GEMM: templated A type, half C output =================
// C[M, 128-blocks](fp16) = A[M,K] @ B[K,N](fp16); block tile 128x128, warp 64x32.
#define ALD 24      // halves
#define BLD 136     // halves
#define SLD 132     // floats, C epilogue tile ld
template <typename TA>
__global__ void __launch_bounds__(256, 2) twmma_kernel(const TA* __restrict__ A,
                                                       const __half* __restrict__ B,
                                                       __half* __restrict__ C,
                                                       int M, int K, int lda, int ldb, int ldc,
                                                       long sB, long sC) {
    constexpr bool AFLOAT = sizeof(TA) == 4;
    extern __shared__ __half hsm[];
    __half* sA = hsm;                       // [2][128*ALD]
    __half* sB_ = hsm + 2 * 128 * ALD;      // [NSTAGE][16*BLD]
    float*  sCf = (float*)hsm;              // [128][SLD] epilogue overlay

    B += (long)blockIdx.z * sB;
    C += (long)blockIdx.z * sC;
    int bm = blockIdx.x * 128;
    int bn = blockIdx.y * 128;

    int tid = threadIdx.x;
    int w = tid >> 5;
    int wm = w & 1;
    int wn = w >> 1;

    wmma::fragment<wmma::accumulator, 16, 16, 16, float> acc[4][2];
#pragma unroll
    for (int i = 0; i < 4; i++)
#pragma unroll
        for (int j = 0; j < 2; j++) wmma::fill_fragment(acc[i][j], 0.f);

    int ar = tid >> 1, ah = (tid & 1) * 8;
    bool ok = (bm + ar) < M;
    const TA* aB = A + (size_t)(bm + ar) * lda + ah;
    float4 ra0, ra1;      // used when AFLOAT
    uint4  rh;            // used when !AFLOAT

    int brow = tid >> 4, bc8 = tid & 15;    // one 16B chunk (8 halves) per thread
    const __half* bBase = B + (size_t)brow * ldb + bn + bc8 * 8;

#define LOADA(kt) do { \
        if constexpr (AFLOAT) { \
            ra0 = ok ? __ldg((const float4*)(aB + (kt)))     : make_float4(0.f, 0.f, 0.f, 0.f); \
            ra1 = ok ? __ldg((const float4*)(aB + (kt) + 4)) : make_float4(0.f, 0.f, 0.f, 0.f); \
        } else { \
            rh = ok ? __ldg((const uint4*)(aB + (kt))) : make_uint4(0u, 0u, 0u, 0u); \
        } \
    } while (0)
#define STOREA(buf) do { \
        __half* s = sA + (buf) * 128 * ALD + ar * ALD + ah; \
        if constexpr (AFLOAT) { \
            ((half2*)s)[0] = __floats2half2_rn(ra0.x, ra0.y); \
            ((half2*)s)[1] = __floats2half2_rn(ra0.z, ra0.w); \
            ((half2*)s)[2] = __floats2half2_rn(ra1.x, ra1.y); \
            ((half2*)s)[3] = __floats2half2_rn(ra1.z, ra1.w); \
        } else { \
            *(uint4*)s = rh; \
        } \
    } while (0)
#define ISSUEB(stage, kt) do { \
        uint32_t d = sptr(sB_ + (stage) * 16 * BLD + brow * BLD + bc8 * 8); \
        CP16(d, bBase + (size_t)(kt) * ldb); \
    } while (0)

    int nk = K >> 4;
#pragma unroll
    for (int s = 0; s < NSTAGE - 1; s++) {
        if (s < nk) ISSUEB(s, s << 4);
        CP_COMMIT();
    }
    LOADA(0);
    STOREA(0);

    for (int i = 0; i < nk; i++) {
        if (i + 1 < nk) LOADA((i + 1) << 4);
        cp_wait<NSTAGE - 2>();
        __syncthreads();
        if (i + NSTAGE - 1 < nk) ISSUEB((i + NSTAGE - 1) % NSTAGE, (i + NSTAGE - 1) << 4);
        CP_COMMIT();

        __half* sa = sA + (i & 1) * 128 * ALD;
        __half* sb = sB_ + (i % NSTAGE) * 16 * BLD;
        wmma::fragment<wmma::matrix_a, 16, 16, 16, __half, wmma::row_major> af[4];
        wmma::fragment<wmma::matrix_b, 16, 16, 16, __half, wmma::row_major> bf[2];
#pragma unroll
        for (int x = 0; x < 4; x++)
            wmma::load_matrix_sync(af[x], sa + (wm * 64 + x * 16) * ALD, ALD);
#pragma unroll
        for (int y = 0; y < 2; y++)
            wmma::load_matrix_sync(bf[y], sb + wn * 32 + y * 16, BLD);
#pragma unroll
        for (int x = 0; x < 4; x++)
#pragma unroll
            for (int y = 0; y < 2; y++)
                wmma::mma_sync(acc[x][y], af[x], bf[y], acc[x][y]);

        if (i + 1 < nk) STOREA((i + 1) & 1);
    }

    // ---- epilogue: acc -> SMEM fp32 tile -> global half ----
    cp_wait<0>();
    __syncthreads();   // staging dead from here
#pragma unroll
    for (int i = 0; i < 4; i++)
#pragma unroll
        for (int j = 0; j < 2; j++)
            wmma::store_matrix_sync(sCf + (wm * 64 + i * 16) * SLD + wn * 32 + j * 16,
                                    acc[i][j], SLD, wmma::mem_row_major);
    __syncthreads();

    {
        int r = tid >> 1;
        int ch = (tid & 1) * 64;
        if (bm + r < M) {
            __half* gp = C + (size_t)(bm + r) * ldc + bn + ch;
            const float* sp = sCf + r * SLD + ch;
#pragma unroll
            for (int q = 0; q < 8; q++) {
                float4 v0 = *(const float4*)(sp + q * 8);
                float4 v1 = *(const float4*)(sp + q * 8 + 4);
                uint4 o;
                half2* op = (half2*)&o;
                op[0] = __floats2half2_rn(v0.x, v0.y);
                op[1] = __floats2half2_rn(v0.z, v0.w);
                op[2] = __floats2half2_rn(v1.x, v1.y);
                op[3] = __floats2half2_rn(v1.z, v1.w);
                *(uint4*)(gp + q * 8) = o;
            }
        }
    }
#undef LOADA
#undef STOREA
#undef ISSUEB
}

// ================= fused edge MLP, fp16 (Hs/Hd in half) =================
#define EALD 24
#define EBLD 264
__global__ void __launch_bounds__(256, 2) edge_fused_kernel(const int* __restrict__ srcv,
                                                            const int* __restrict__ dstv,
                                                            const float* __restrict__ etext,
                                                            const __half* __restrict__ Wt,
                                                            const float* __restrict__ b1v,
                                                            const float* __restrict__ w2v,
                                                            const float* __restrict__ b2v,
                                                            const __half* __restrict__ Hs,
                                                            const __half* __restrict__ Hd,
                                                            float* __restrict__ logits) {
    extern __shared__ __half hsm[];
    __half* sA = hsm;                       // [2][64*EALD]
    __half* sB = hsm + 2 * 64 * EALD;       // [NSTAGE][16*EBLD]
    float*  sC = (float*)hsm;               // [64][256] fp32 overlay

    int tid = threadIdx.x;
    int w = tid >> 5, lane = tid & 31;
    int bm = blockIdx.x * 64;

    wmma::fragment<wmma::accumulator, 16, 16, 16, float> acc[4][2];
#pragma unroll
    for (int i = 0; i < 4; i++)
#pragma unroll
        for (int j = 0; j < 2; j++) wmma::fill_fragment(acc[i][j], 0.f);

    int ar = tid >> 2, aq = (tid & 3) * 4;
    const float* aB = etext + (size_t)(bm + ar) * 256 + aq;
    float4 ra;

    int brow = tid >> 4, bc16 = (tid & 15) * 16;
    const __half* bBase = Wt + (size_t)brow * 256 + bc16;

#define ELOADA(kt)  do { ra = __ldg((const float4*)(aB + (kt))); } while (0)
#define ESTOREA(buf) do { \
        __half* s = sA + (buf) * 64 * EALD + ar * EALD + aq; \
        ((half2*)s)[0] = __floats2half2_rn(ra.x, ra.y); \
        ((half2*)s)[1] = __floats2half2_rn(ra.z, ra.w); \
    } while (0)
#define EISSUEB(stage, kt) do { \
        uint32_t d = sptr(sB + (stage) * 16 * EBLD + brow * EBLD + bc16); \
        const __half* sgp = bBase + (size_t)(kt) * 256; \
        CP16(d, sgp); CP16(d + 16, sgp + 8); \
    } while (0)

    const int nk = 16;
#pragma unroll
    for (int s = 0; s < NSTAGE - 1; s++) {
        EISSUEB(s, s << 4);
        CP_COMMIT();
    }
    ELOADA(0);
    ESTOREA(0);

    for (int i = 0; i < nk; i++) {
        if (i + 1 < nk) ELOADA((i + 1) << 4);
        cp_wait<NSTAGE - 2>();
        __syncthreads();
        if (i + NSTAGE - 1 < nk) EISSUEB((i + NSTAGE - 1) % NSTAGE, (i + NSTAGE - 1) << 4);
        CP_COMMIT();

        __half* sa = sA + (i & 1) * 64 * EALD;
        __half* sb = sB + (i % NSTAGE) * 16 * EBLD;
        wmma::fragment<wmma::matrix_a, 16, 16, 16, __half, wmma::row_major> af[4];
        wmma::fragment<wmma::matrix_b, 16, 16, 16, __half, wmma::row_major> bf[2];
#pragma unroll
        for (int x = 0; x < 4; x++)
            wmma::load_matrix_sync(af[x], sa + (x * 16) * EALD, EALD);
#pragma unroll
        for (int y = 0; y < 2; y++)
            wmma::load_matrix_sync(bf[y], sb + w * 32 + y * 16, EBLD);
#pragma unroll
        for (int x = 0; x < 4; x++)
#pragma unroll
            for (int y = 0; y < 2; y++)
                wmma::mma_sync(acc[x][y], af[x], bf[y], acc[x][y]);

        if (i + 1 < nk) ESTOREA((i + 1) & 1);
    }

    cp_wait<0>();
    __syncthreads();
#pragma unroll
    for (int i = 0; i < 4; i++)
#pragma unroll
        for (int j = 0; j < 2; j++)
            wmma::store_matrix_sync(sC + (i * 16) * 256 + w * 32 + j * 16, acc[i][j],
                                    256, wmma::mem_row_major);
    __syncthreads();

    int c0 = lane * 8;
    float4 b1a = __ldg((const float4*)(b1v + c0));
    float4 b1b = __ldg((const float4*)(b1v + c0 + 4));
    float4 w2a = __ldg((const float4*)(w2v + c0));
    float4 w2b = __ldg((const float4*)(w2v + c0 + 4));
    float beta = __ldg(b2v);

#pragma unroll
    for (int ei = 0; ei < 8; ei++) {
        int el = w * 8 + ei;
        int e = bm + el;
        int s = __ldg(srcv + e), d = __ldg(dstv + e);
        float4 ca = *(float4*)(sC + el * 256 + c0);
        float4 cb = *(float4*)(sC + el * 256 + c0 + 4);
        uint4 hsv = __ldg((const uint4*)(Hs + (size_t)s * 256 + c0));
        uint4 hdv = __ldg((const uint4*)(Hd + (size_t)d * 256 + c0));
        half2* hsp = (half2*)&hsv;
        half2* hdp = (half2*)&hdv;
        float2 hs0 = __half22float2(hsp[0]), hs1 = __half22float2(hsp[1]);
        float2 hs2 = __half22float2(hsp[2]), hs3 = __half22float2(hsp[3]);
        float2 hd0 = __half22float2(hdp[0]), hd1 = __half22float2(hdp[1]);
        float2 hd2 = __half22float2(hdp[2]), hd3 = __half22float2(hdp[3]);
        float p = 0.f, h;
        h = fmaxf(ca.x + hs0.x + hd0.x + b1a.x, 0.f); p = fmaf(h, w2a.x, p);
        h = fmaxf(ca.y + hs0.y + hd0.y + b1a.y, 0.f); p = fmaf(h, w2a.y, p);
        h = fmaxf(ca.z + hs1.x + hd1.x + b1a.z, 0.f); p = fmaf(h, w2a.z, p);
        h = fmaxf(ca.w + hs1.y + hd1.y + b1a.w, 0.f); p = fmaf(h, w2a.w, p);
        h = fmaxf(cb.x + hs2.x + hd2.x + b1b.x, 0.f); p = fmaf(h, w2b.x, p);
        h = fmaxf(cb.y + hs2.y + hd2.y + b1b.y, 0.f); p = fmaf(h, w2b.y, p);
        h = fmaxf(cb.z + hs3.x + hd3.x + b1b.z, 0.f); p = fmaf(h, w2b.z, p);
        h = fmaxf(cb.w + hs3.y + hd3.y + b1b.w, 0.f); p = fmaf(h, w2b.w, p);
#pragma unroll
        for (int off = 16; off > 0; off >>= 1)
            p += __shfl_down_sync(0xffffffffu, p, off);
        if (lane == 0) logits[e] = p + beta;
    }
#undef ELOADA
#undef ESTOREA
#undef EISSUEB
}

// ================= CSR build (by dst) =================
__global__ void zeroi_kernel(int* p, int n) {
    int i = blockIdx.x * blockDim.x + threadIdx.x;
    if (i < n) p[i] = 0;
}
__global__ void count_kernel(const int* __restrict__ dstv, const int* __restrict__ etype) {
    int e = blockIdx.x * blockDim.x + threadIdx.x;
    if (e < NE) atomicAdd(&g_cnt[dstv[e] * RREL + etype[e]], 1);
}
__global__ void inv_deg_kernel() {
    int d = blockIdx.x * blockDim.x + threadIdx.x;
    if (d >= NN) return;
    int tot = 0;
#pragma unroll
    for (int r = 0; r < RREL; r++) {
        int c = g_cnt[d * RREL + r];
        tot += c;
        g_inv[d * RREL + r] = c > 0 ? 1.0f / (float)c : 0.0f;
    }
    g_deg[d] = tot;
}
// hierarchical scan of g_deg -> g_off (exclusive)
__global__ void scan1_kernel() {
    __shared__ int s[1024];
    int tid = threadIdx.x;
    int i = blockIdx.x * 1024 + tid;
    int v = (i < NN) ? g_deg[i] : 0;
    s[tid] = v;
    __syncthreads();
    for (int o = 1; o < 1024; o <<= 1) {
        int x = (tid >= o) ? s[tid - o] : 0;
        __syncthreads();
        s[tid] += x;
        __syncthreads();
    }
    if (i < NN) g_off[i] = s[tid] - v;
    if (tid == 1023) g_bsum[blockIdx.x] = s[1023];
}
__global__ void scan2_kernel(int nb) {
    __shared__ int s[64];
    int tid = threadIdx.x;
    int v = (tid < nb) ? g_bsum[tid] : 0;
    s[tid] = v;
    __syncthreads();
    for (int o = 1; o < 64; o <<= 1) {
        int x = (tid >= o) ? s[tid - o] : 0;
        __syncthreads();
        s[tid] += x;
        __syncthreads();
    }
    if (tid < nb) g_bsum[tid] = s[tid] - v;
}
__global__ void scan3_kernel() {
    int i = blockIdx.x * blockDim.x + threadIdx.x;
    if (i < NN) g_off[i] += g_bsum[i >> 10];
    if (i == NN) g_off[NN] = NE;
}
__global__ void fill_kernel(const int* __restrict__ srcv, const int* __restrict__ dstv,
                            const int* __restrict__ etype) {
    int e = blockIdx.x * blockDim.x + threadIdx.x;
    if (e >= NE) return;
    int d = dstv[e];
    int pos = g_off[d] + atomicAdd(&g_cur[d], 1);
    g_eidx[pos] = (srcv[e] << 3) | etype[e];
}

// ================= CSR aggregation: out = relu(root + mean-sum + bias) =================
// xW rows widened to STRIDE: relation blocks at r*D, root at RREL*D.
template <int D, int STRIDE, bool WF>
__global__ void __launch_bounds__(256) agg_kernel(const __half* __restrict__ xW,
                                                  const float* __restrict__ bias,
                                                  __half* __restrict__ outh,
                                                  float* __restrict__ outf) {
    constexpr int TPD = D / 8;                    // 32 or 16
    int d = blockIdx.x * (256 / TPD) + threadIdx.x / TPD;
    int c = threadIdx.x % TPD;
    if (d >= NN) return;
    int beg = __ldg(g_off + d), end = __ldg(g_off + d + 1);
    float a[8] = {0.f, 0.f, 0.f, 0.f, 0.f, 0.f, 0.f, 0.f};
    for (int j = beg; j < end; j++) {
        int pk = __ldg(g_eidx + j);
        float wgt = __ldg(g_inv + d * RREL + (pk & 7));
        uint4 v = __ldg((const uint4*)(xW + (size_t)(pk >> 3) * STRIDE + (pk & 7) * D) + c);
        half2* vp = (half2*)&v;
#pragma unroll
        for (int k = 0; k < 4; k++) {
            float2 f = __half22float2(vp[k]);
            a[2 * k]     = fmaf(wgt, f.x, a[2 * k]);
            a[2 * k + 1] = fmaf(wgt, f.y, a[2 * k + 1]);
        }
    }
    uint4 bv = __ldg((const uint4*)(xW + (size_t)d * STRIDE + RREL * D) + c);
    half2* bp = (half2*)&bv;
    float4 bb0 = __ldg((const float4*)(bias + c * 8));
    float4 bb1 = __ldg((const float4*)(bias + c * 8 + 4));
    float bbv[8] = {bb0.x, bb0.y, bb0.z, bb0.w, bb1.x, bb1.y, bb1.z, bb1.w};
    float o[8];
#pragma unroll
    for (int k = 0; k < 4; k++) {
        float2 f = __half22float2(bp[k]);
        o[2 * k]     = fmaxf(a[2 * k] + f.x + bbv[2 * k], 0.f);
        o[2 * k + 1] = fmaxf(a[2 * k + 1] + f.y + bbv[2 * k + 1], 0.f);
    }
    uint4 ov;
    half2* op = (half2*)&ov;
#pragma unroll
    for (int k = 0; k < 4; k++) op[k] = __floats2half2_rn(o[2 * k], o[2 * k + 1]);
    *((uint4*)(outh + (size_t)d * D) + c) = ov;
    if (WF) {
        float4* fo = (float4*)(outf + (size_t)d * D + c * 8);
        fo[0] = make_float4(o[0], o[1], o[2], o[3]);
        fo[1] = make_float4(o[4], o[5], o[6], o[7]);
    }
}

// ================= utility =================
__global__ void half_copy_kernel(const float4* __restrict__ src, __half* __restrict__ dst, int n4) {
    int i = blockIdx.x * blockDim.x + threadIdx.x;
    if (i < n4) {
        float4 v = src[i];
        __half* d = dst + (size_t)i * 4;
        ((half2*)d)[0] = __floats2half2_rn(v.x, v.y);
        ((half2*)d)[1] = __floats2half2_rn(v.z, v.w);
    }
}

// ================= launch =================
extern "C" void kernel_launch(void* const* d_in, const int* in_sizes, int n_in,
                              void* d_out, int out_size) {
    const int*   edge_index = (const int*)d_in[0];
    const int*   etype      = (const int*)d_in[1];
    const float* etext      = (const float*)d_in[2];
    const float* node_emb   = (const float*)d_in[3];
    const float* W1         = (const float*)d_in[4];
    const float* root1      = (const float*)d_in[5];
    const float* b1         = (const float*)d_in[6];
    const float* W2         = (const float*)d_in[7];
    const float* root2      = (const float*)d_in[8];
    const float* b2         = (const float*)d_in[9];
    const float* mlpW1      = (const float*)d_in[10];
    const float* mlpb1      = (const float*)d_in[11];
    const float* mlpW2      = (const float*)d_in[12];
    const float* mlpb2      = (const float*)d_in[13];

    const int* srcv = edge_index;
    const int* dstv = edge_index + NE;
    float* logits = (float*)d_out;
    float* h2out  = (float*)d_out + NE;

    void* p;
    cudaGetSymbolAddress(&p, g_cnt);  int*    cntp = (int*)p;
    cudaGetSymbolAddress(&p, g_cur);  int*    curp = (int*)p;
    cudaGetSymbolAddress(&p, g_xWh);  __half* xWh  = (__half*)p;
    cudaGetSymbolAddress(&p, g_xh);   __half* xh   = (__half*)p;
    cudaGetSymbolAddress(&p, g_h1h);  __half* h1h  = (__half*)p;
    cudaGetSymbolAddress(&p, g_h2h);  __half* h2h  = (__half*)p;
    cudaGetSymbolAddress(&p, g_Hh);   __half* Hh   = (__half*)p;
    cudaGetSymbolAddress(&p, g_wt);   __half* wt   = (__half*)p;

    const int GSMEM = 128 * SLD * 4;    // 67584 (>= staging 29696)
    const int ESMEM = 64 * 256 * 4;     // 65536 (>= staging 39936)
    cudaFuncSetAttribute(twmma_kernel<float>, cudaFuncAttributeMaxDynamicSharedMemorySize, GSMEM);
    cudaFuncSetAttribute(twmma_kernel<__half>, cudaFuncAttributeMaxDynamicSharedMemorySize, GSMEM);
    cudaFuncSetAttribute(edge_fused_kernel, cudaFuncAttributeMaxDynamicSharedMemorySize, ESMEM);

    // weight + input conversion to fp16
    half_copy_kernel<<<512, 256>>>((const float4*)W1, wt + OFF_W1, 524288 / 4);
    half_copy_kernel<<<64, 256>>>((const float4*)root1, wt + OFF_R1, 65536 / 4);
    half_copy_kernel<<<256, 256>>>((const float4*)W2, wt + OFF_W2, 262144 / 4);
    half_copy_kernel<<<32, 256>>>((const float4*)root2, wt + OFF_R2, 32768 / 4);
    half_copy_kernel<<<128, 256>>>((const float4*)mlpW1, wt + OFF_M1, 131072 / 4);
    half_copy_kernel<<<(NN * 64 + 255) / 256, 256>>>((const float4*)node_emb, xh, NN * 64);

    // CSR build
    zeroi_kernel<<<(NN * RREL + 255) / 256, 256>>>(cntp, NN * RREL);
    zeroi_kernel<<<(NN + 255) / 256, 256>>>(curp, NN);
    count_kernel<<<(NE + 255) / 256, 256>>>(dstv, etype);
    inv_deg_kernel<<<(NN + 255) / 256, 256>>>();
    const int NB = (NN + 1023) / 1024;   // 49
    scan1_kernel<<<NB, 1024>>>();
    scan2_kernel<<<1, 64>>>(NB);
    scan3_kernel<<<(NN + 256) / 256, 256>>>();
    fill_kernel<<<(NE + 255) / 256, 256>>>(srcv, dstv, etype);

    const int MB = NP / 128;  // 391

    // ---- layer 1: one z=9 launch (8 relations + root) into widened xW rows ----
    twmma_kernel<__half><<<dim3(MB, 2, 9), 256, GSMEM>>>(xh, wt + OFF_W1, xWh,
                                                         NN, 256, 256, 256, 2304,
                                                         65536L, 256L);
    agg_kernel<256, 2304, false><<<(NN + 7) / 8, 256>>>(xWh, b1, h1h, nullptr);

    // ---- layer 2: one z=9 launch into rows of width 1152 ----
    twmma_kernel<__half><<<dim3(MB, 1, 9), 256, GSMEM>>>(h1h, wt + OFF_W2, xWh,
                                                         NN, 256, 256, 128, 1152,
                                                         32768L, 128L);
    agg_kernel<128, 1152, true><<<(NN + 15) / 16, 256>>>(xWh, b2, h2h, h2out);

    // ---- edge MLP: Hs|Hd in one z=2 launch, then fused edge kernel ----
    twmma_kernel<__half><<<dim3(MB, 2, 2), 256, GSMEM>>>(h2h, wt + OFF_M1, Hh,
                                                         NN, 128, 128, 256, 256,
                                                         32768L, (long)NP * 256);
    edge_fused_kernel<<<NE / 64, 256, ESMEM>>>(srcv, dstv, etext, wt + OFF_M1 + 65536,
                                               mlpb1, mlpW2, mlpb2,
                                               Hh, Hh + (size_t)NP * 256, logits);
}

// round 14
// speedup vs baseline: 1.1595x; 1.0136x over previous
#include <cuda_runtime.h>
#include <cuda_fp16.h>
#include <mma.h>
#include <cstdint>

using namespace nvcuda;

#define NN 50000
#define NP 50048        // padded rows: 391 * 128
#define NE 800000
#define RREL 8
#define NSTAGE 4

// ---------------- static device scratch ----------------
__device__ int    g_cnt[NN * RREL];
__device__ float  g_inv[NN * RREL];
__device__ int    g_deg[NN];
__device__ int    g_off[NN + 1];
__device__ int    g_cur[NN];
__device__ int    g_eidx[NE];
__device__ int    g_bsum[64];
__device__ __half g_xWh[(size_t)NP * 2304];   // widened rows: 8 relations + root
__device__ __half g_xh[NN * 256];             // node_emb in fp16
__device__ __half g_h1h[NP * 256];
__device__ __half g_h2h[NP * 128];
__device__ __half g_Hh[2 * (size_t)NP * 256]; // Hs | Hd (half)
__device__ __half g_wt[1015808];              // fp16 weights

#define OFF_W1 0        // W1 [8][256][256] then root1 (contiguous)
#define OFF_R1 524288
#define OFF_W2 589824   // W2 [8][256][128] then root2 (contiguous)
#define OFF_R2 851968
#define OFF_M1 884736   // mlpW1 (512x256): Hs rows 0:128, Hd 128:256, Wt 256:512

#define CP16(dst, src) \
    asm volatile("cp.async.cg.shared.global [%0], [%1], 16;" :: "r"(dst), "l"(src))
#define CP_COMMIT() asm volatile("cp.async.commit_group;" ::: "memory")
template <int N>
__device__ __forceinline__ void cp_wait() {
    asm volatile("cp.async.wait_group %0;" :: "n"(N) : "memory");
}
__device__ __forceinline__ uint32_t sptr(const void* p) {
    return (uint32_t)__cvta_generic_to_shared(p);
}

// ================= wmma fp16 GEMM (unchanged from R13) =================
#define ALD 24      // halves
#define BLD 136     // halves
#define SLD 132     // floats, C epilogue tile ld
template <typename TA>
__global__ void __launch_bounds__(256, 2) twmma_kernel(const TA* __restrict__ A,
                                                       const __half* __restrict__ B,
                                                       __half* __restrict__ C,
                                                       int M, int K, int lda, int ldb, int ldc,
                                                       long sB, long sC) {
    constexpr bool AFLOAT = sizeof(TA) == 4;
    extern __shared__ __half hsm[];
    __half* sA = hsm;
    __half* sB_ = hsm + 2 * 128 * ALD;
    float*  sCf = (float*)hsm;

    B += (long)blockIdx.z * sB;
    C += (long)blockIdx.z * sC;
    int bm = blockIdx.x * 128;
    int bn = blockIdx.y * 128;

    int tid = threadIdx.x;
    int w = tid >> 5;
    int wm = w & 1;
    int wn = w >> 1;

    wmma::fragment<wmma::accumulator, 16, 16, 16, float> acc[4][2];
#pragma unroll
    for (int i = 0; i < 4; i++)
#pragma unroll
        for (int j = 0; j < 2; j++) wmma::fill_fragment(acc[i][j], 0.f);

    int ar = tid >> 1, ah = (tid & 1) * 8;
    bool ok = (bm + ar) < M;
    const TA* aB = A + (size_t)(bm + ar) * lda + ah;
    float4 ra0, ra1;
    uint4  rh;

    int brow = tid >> 4, bc8 = tid & 15;
    const __half* bBase = B + (size_t)brow * ldb + bn + bc8 * 8;

#define LOADA(kt) do { \
        if constexpr (AFLOAT) { \
            ra0 = ok ? __ldg((const float4*)(aB + (kt)))     : make_float4(0.f, 0.f, 0.f, 0.f); \
            ra1 = ok ? __ldg((const float4*)(aB + (kt) + 4)) : make_float4(0.f, 0.f, 0.f, 0.f); \
        } else { \
            rh = ok ? __ldg((const uint4*)(aB + (kt))) : make_uint4(0u, 0u, 0u, 0u); \
        } \
    } while (0)
#define STOREA(buf) do { \
        __half* s = sA + (buf) * 128 * ALD + ar * ALD + ah; \
        if constexpr (AFLOAT) { \
            ((half2*)s)[0] = __floats2half2_rn(ra0.x, ra0.y); \
            ((half2*)s)[1] = __floats2half2_rn(ra0.z, ra0.w); \
            ((half2*)s)[2] = __floats2half2_rn(ra1.x, ra1.y); \
            ((half2*)s)[3] = __floats2half2_rn(ra1.z, ra1.w); \
        } else { \
            *(uint4*)s = rh; \
        } \
    } while (0)
#define ISSUEB(stage, kt) do { \
        uint32_t d = sptr(sB_ + (stage) * 16 * BLD + brow * BLD + bc8 * 8); \
        CP16(d, bBase + (size_t)(kt) * ldb); \
    } while (0)

    int nk = K >> 4;
#pragma unroll
    for (int s = 0; s < NSTAGE - 1; s++) {
        if (s < nk) ISSUEB(s, s << 4);
        CP_COMMIT();
    }
    LOADA(0);
    STOREA(0);

    for (int i = 0; i < nk; i++) {
        if (i + 1 < nk) LOADA((i + 1) << 4);
        cp_wait<NSTAGE - 2>();
        __syncthreads();
        if (i + NSTAGE - 1 < nk) ISSUEB((i + NSTAGE - 1) % NSTAGE, (i + NSTAGE - 1) << 4);
        CP_COMMIT();

        __half* sa = sA + (i & 1) * 128 * ALD;
        __half* sb = sB_ + (i % NSTAGE) * 16 * BLD;
        wmma::fragment<wmma::matrix_a, 16, 16, 16, __half, wmma::row_major> af[4];
        wmma::fragment<wmma::matrix_b, 16, 16, 16, __half, wmma::row_major> bf[2];
#pragma unroll
        for (int x = 0; x < 4; x++)
            wmma::load_matrix_sync(af[x], sa + (wm * 64 + x * 16) * ALD, ALD);
#pragma unroll
        for (int y = 0; y < 2; y++)
            wmma::load_matrix_sync(bf[y], sb + wn * 32 + y * 16, BLD);
#pragma unroll
        for (int x = 0; x < 4; x++)
#pragma unroll
            for (int y = 0; y < 2; y++)
                wmma::mma_sync(acc[x][y], af[x], bf[y], acc[x][y]);

        if (i + 1 < nk) STOREA((i + 1) & 1);
    }

    cp_wait<0>();
    __syncthreads();
#pragma unroll
    for (int i = 0; i < 4; i++)
#pragma unroll
        for (int j = 0; j < 2; j++)
            wmma::store_matrix_sync(sCf + (wm * 64 + i * 16) * SLD + wn * 32 + j * 16,
                                    acc[i][j], SLD, wmma::mem_row_major);
    __syncthreads();

    {
        int r = tid >> 1;
        int ch = (tid & 1) * 64;
        if (bm + r < M) {
            __half* gp = C + (size_t)(bm + r) * ldc + bn + ch;
            const float* sp = sCf + r * SLD + ch;
#pragma unroll
            for (int q = 0; q < 8; q++) {
                float4 v0 = *(const float4*)(sp + q * 8);
                float4 v1 = *(const float4*)(sp + q * 8 + 4);
                uint4 o;
                half2* op = (half2*)&o;
                op[0] = __floats2half2_rn(v0.x, v0.y);
                op[1] = __floats2half2_rn(v0.z, v0.w);
                op[2] = __floats2half2_rn(v1.x, v1.y);
                op[3] = __floats2half2_rn(v1.z, v1.w);
                *(uint4*)(gp + q * 8) = o;
            }
        }
    }
#undef LOADA
#undef STOREA
#undef ISSUEB
}

// ================= fused edge MLP (unchanged from R13) =================
#define EALD 24
#define EBLD 264
__global__ void __launch_bounds__(256, 2) edge_fused_kernel(const int* __restrict__ srcv,
                                                            const int* __restrict__ dstv,
                                                            const float* __restrict__ etext,
                                                            const __half* __restrict__ Wt,
                                                            const float* __restrict__ b1v,
                                                            const float* __restrict__ w2v,
                                                            const float* __restrict__ b2v,
                                                            const __half* __restrict__ Hs,
                                                            const __half* __restrict__ Hd,
                                                            float* __restrict__ logits) {
    extern __shared__ __half hsm[];
    __half* sA = hsm;
    __half* sB = hsm + 2 * 64 * EALD;
    float*  sC = (float*)hsm;

    int tid = threadIdx.x;
    int w = tid >> 5, lane = tid & 31;
    int bm = blockIdx.x * 64;

    wmma::fragment<wmma::accumulator, 16, 16, 16, float> acc[4][2];
#pragma unroll
    for (int i = 0; i < 4; i++)
#pragma unroll
        for (int j = 0; j < 2; j++) wmma::fill_fragment(acc[i][j], 0.f);

    int ar = tid >> 2, aq = (tid & 3) * 4;
    const float* aB = etext + (size_t)(bm + ar) * 256 + aq;
    float4 ra;

    int brow = tid >> 4, bc16 = (tid & 15) * 16;
    const __half* bBase = Wt + (size_t)brow * 256 + bc16;

#define ELOADA(kt)  do { ra = __ldg((const float4*)(aB + (kt))); } while (0)
#define ESTOREA(buf) do { \
        __half* s = sA + (buf) * 64 * EALD + ar * EALD + aq; \
        ((half2*)s)[0] = __floats2half2_rn(ra.x, ra.y); \
        ((half2*)s)[1] = __floats2half2_rn(ra.z, ra.w); \
    } while (0)
#define EISSUEB(stage, kt) do { \
        uint32_t d = sptr(sB + (stage) * 16 * EBLD + brow * EBLD + bc16); \
        const __half* sgp = bBase + (size_t)(kt) * 256; \
        CP16(d, sgp); CP16(d + 16, sgp + 8); \
    } while (0)

    const int nk = 16;
#pragma unroll
    for (int s = 0; s < NSTAGE - 1; s++) {
        EISSUEB(s, s << 4);
        CP_COMMIT();
    }
    ELOADA(0);
    ESTOREA(0);

    for (int i = 0; i < nk; i++) {
        if (i + 1 < nk) ELOADA((i + 1) << 4);
        cp_wait<NSTAGE - 2>();
        __syncthreads();
        if (i + NSTAGE - 1 < nk) EISSUEB((i + NSTAGE - 1) % NSTAGE, (i + NSTAGE - 1) << 4);
        CP_COMMIT();

        __half* sa = sA + (i & 1) * 64 * EALD;
        __half* sb = sB + (i % NSTAGE) * 16 * EBLD;
        wmma::fragment<wmma::matrix_a, 16, 16, 16, __half, wmma::row_major> af[4];
        wmma::fragment<wmma::matrix_b, 16, 16, 16, __half, wmma::row_major> bf[2];
#pragma unroll
        for (int x = 0; x < 4; x++)
            wmma::load_matrix_sync(af[x], sa + (x * 16) * EALD, EALD);
#pragma unroll
        for (int y = 0; y < 2; y++)
            wmma::load_matrix_sync(bf[y], sb + w * 32 + y * 16, EBLD);
#pragma unroll
        for (int x = 0; x < 4; x++)
#pragma unroll
            for (int y = 0; y < 2; y++)
                wmma::mma_sync(acc[x][y], af[x], bf[y], acc[x][y]);

        if (i + 1 < nk) ESTOREA((i + 1) & 1);
    }

    cp_wait<0>();
    __syncthreads();
#pragma unroll
    for (int i = 0; i < 4; i++)
#pragma unroll
        for (int j = 0; j < 2; j++)
            wmma::store_matrix_sync(sC + (i * 16) * 256 + w * 32 + j * 16, acc[i][j],
                                    256, wmma::mem_row_major);
    __syncthreads();

    int c0 = lane * 8;
    float4 b1a = __ldg((const float4*)(b1v + c0));
    float4 b1b = __ldg((const float4*)(b1v + c0 + 4));
    float4 w2a = __ldg((const float4*)(w2v + c0));
    float4 w2b = __ldg((const float4*)(w2v + c0 + 4));
    float beta = __ldg(b2v);

#pragma unroll
    for (int ei = 0; ei < 8; ei++) {
        int el = w * 8 + ei;
        int e = bm + el;
        int s = __ldg(srcv + e), d = __ldg(dstv + e);
        float4 ca = *(float4*)(sC + el * 256 + c0);
        float4 cb = *(float4*)(sC + el * 256 + c0 + 4);
        uint4 hsv = __ldg((const uint4*)(Hs + (size_t)s * 256 + c0));
        uint4 hdv = __ldg((const uint4*)(Hd + (size_t)d * 256 + c0));
        half2* hsp = (half2*)&hsv;
        half2* hdp = (half2*)&hdv;
        float2 hs0 = __half22float2(hsp[0]), hs1 = __half22float2(hsp[1]);
        float2 hs2 = __half22float2(hsp[2]), hs3 = __half22float2(hsp[3]);
        float2 hd0 = __half22float2(hdp[0]), hd1 = __half22float2(hdp[1]);
        float2 hd2 = __half22float2(hdp[2]), hd3 = __half22float2(hdp[3]);
        float p = 0.f, h;
        h = fmaxf(ca.x + hs0.x + hd0.x + b1a.x, 0.f); p = fmaf(h, w2a.x, p);
        h = fmaxf(ca.y + hs0.y + hd0.y + b1a.y, 0.f); p = fmaf(h, w2a.y, p);
        h = fmaxf(ca.z + hs1.x + hd1.x + b1a.z, 0.f); p = fmaf(h, w2a.z, p);
        h = fmaxf(ca.w + hs1.y + hd1.y + b1a.w, 0.f); p = fmaf(h, w2a.w, p);
        h = fmaxf(cb.x + hs2.x + hd2.x + b1b.x, 0.f); p = fmaf(h, w2b.x, p);
        h = fmaxf(cb.y + hs2.y + hd2.y + b1b.y, 0.f); p = fmaf(h, w2b.y, p);
        h = fmaxf(cb.z + hs3.x + hd3.x + b1b.z, 0.f); p = fmaf(h, w2b.z, p);
        h = fmaxf(cb.w + hs3.y + hd3.y + b1b.w, 0.f); p = fmaf(h, w2b.w, p);
#pragma unroll
        for (int off = 16; off > 0; off >>= 1)
            p += __shfl_down_sync(0xffffffffu, p, off);
        if (lane == 0) logits[e] = p + beta;
    }
#undef ELOADA
#undef ESTOREA
#undef EISSUEB
}

// ================= CSR build (by dst) =================
__global__ void zeroi_kernel(int* p, int n) {
    int i = blockIdx.x * blockDim.x + threadIdx.x;
    if (i < n) p[i] = 0;
}
__global__ void count_kernel(const int* __restrict__ dstv, const int* __restrict__ etype) {
    int e = blockIdx.x * blockDim.x + threadIdx.x;
    if (e < NE) atomicAdd(&g_cnt[dstv[e] * RREL + etype[e]], 1);
}
__global__ void inv_deg_kernel() {
    int d = blockIdx.x * blockDim.x + threadIdx.x;
    if (d >= NN) return;
    int tot = 0;
#pragma unroll
    for (int r = 0; r < RREL; r++) {
        int c = g_cnt[d * RREL + r];
        tot += c;
        g_inv[d * RREL + r] = c > 0 ? 1.0f / (float)c : 0.0f;
    }
    g_deg[d] = tot;
    g_cur[d] = 0;
}
__global__ void scan1_kernel() {
    __shared__ int s[1024];
    int tid = threadIdx.x;
    int i = blockIdx.x * 1024 + tid;
    int v = (i < NN) ? g_deg[i] : 0;
    s[tid] = v;
    __syncthreads();
    for (int o = 1; o < 1024; o <<= 1) {
        int x = (tid >= o) ? s[tid - o] : 0;
        __syncthreads();
        s[tid] += x;
        __syncthreads();
    }
    if (i < NN) g_off[i] = s[tid] - v;
    if (tid == 1023) g_bsum[blockIdx.x] = s[1023];
}
__global__ void scan2_kernel(int nb) {
    __shared__ int s[64];
    int tid = threadIdx.x;
    int v = (tid < nb) ? g_bsum[tid] : 0;
    s[tid] = v;
    __syncthreads();
    for (int o = 1; o < 64; o <<= 1) {
        int x = (tid >= o) ? s[tid - o] : 0;
        __syncthreads();
        s[tid] += x;
        __syncthreads();
    }
    if (tid < nb) g_bsum[tid] = s[tid] - v;
}
__global__ void scan3_kernel() {
    int i = blockIdx.x * blockDim.x + threadIdx.x;
    if (i < NN) g_off[i] += g_bsum[i >> 10];
    if (i == NN) g_off[NN] = NE;
}
__global__ void fill_kernel(const int* __restrict__ srcv, const int* __restrict__ dstv,
                            const int* __restrict__ etype) {
    int e = blockIdx.x * blockDim.x + threadIdx.x;
    if (e >= NE) return;
    int d = dstv[e];
    int pos = g_off[d] + atomicAdd(&g_cur[d], 1);
    g_eidx[pos] = (srcv[e] << 3) | etype[e];
}

// ================= CSR aggregation (unchanged from R13) =================
template <int D, int STRIDE, bool WF>
__global__ void __launch_bounds__(256) agg_kernel(const __half* __restrict__ xW,
                                                  const float* __restrict__ bias,
                                                  __half* __restrict__ outh,
                                                  float* __restrict__ outf) {
    constexpr int TPD = D / 8;
    int d = blockIdx.x * (256 / TPD) + threadIdx.x / TPD;
    int c = threadIdx.x % TPD;
    if (d >= NN) return;
    int beg = __ldg(g_off + d), end = __ldg(g_off + d + 1);
    float a[8] = {0.f, 0.f, 0.f, 0.f, 0.f, 0.f, 0.f, 0.f};
    for (int j = beg; j < end; j++) {
        int pk = __ldg(g_eidx + j);
        float wgt = __ldg(g_inv + d * RREL + (pk & 7));
        uint4 v = __ldg((const uint4*)(xW + (size_t)(pk >> 3) * STRIDE + (pk & 7) * D) + c);
        half2* vp = (half2*)&v;
#pragma unroll
        for (int k = 0; k < 4; k++) {
            float2 f = __half22float2(vp[k]);
            a[2 * k]     = fmaf(wgt, f.x, a[2 * k]);
            a[2 * k + 1] = fmaf(wgt, f.y, a[2 * k + 1]);
        }
    }
    uint4 bv = __ldg((const uint4*)(xW + (size_t)d * STRIDE + RREL * D) + c);
    half2* bp = (half2*)&bv;
    float4 bb0 = __ldg((const float4*)(bias + c * 8));
    float4 bb1 = __ldg((const float4*)(bias + c * 8 + 4));
    float bbv[8] = {bb0.x, bb0.y, bb0.z, bb0.w, bb1.x, bb1.y, bb1.z, bb1.w};
    float o[8];
#pragma unroll
    for (int k = 0; k < 4; k++) {
        float2 f = __half22float2(bp[k]);
        o[2 * k]     = fmaxf(a[2 * k] + f.x + bbv[2 * k], 0.f);
        o[2 * k + 1] = fmaxf(a[2 * k + 1] + f.y + bbv[2 * k + 1], 0.f);
    }
    uint4 ov;
    half2* op = (half2*)&ov;
#pragma unroll
    for (int k = 0; k < 4; k++) op[k] = __floats2half2_rn(o[2 * k], o[2 * k + 1]);
    *((uint4*)(outh + (size_t)d * D) + c) = ov;
    if (WF) {
        float4* fo = (float4*)(outf + (size_t)d * D + c * 8);
        fo[0] = make_float4(o[0], o[1], o[2], o[3]);
        fo[1] = make_float4(o[4], o[5], o[6], o[7]);
    }
}

// ================= fused fp32->fp16 conversion of all params + node_emb =================
// segment boundaries in float4 units
#define C_S0 131072    // W1
#define C_S1 147456    // + root1
#define C_S2 212992    // + W2
#define C_S3 221184    // + root2
#define C_S4 253952    // + mlpW1
#define C_S5 3453952   // + node_emb
__global__ void convert_all_kernel(const float4* __restrict__ W1, const float4* __restrict__ r1,
                                   const float4* __restrict__ W2, const float4* __restrict__ r2,
                                   const float4* __restrict__ m1, const float4* __restrict__ xe,
                                   __half* __restrict__ wt, __half* __restrict__ xh) {
    int i = blockIdx.x * blockDim.x + threadIdx.x;
    if (i >= C_S5) return;
    const float4* src;
    __half* dst;
    int off;
    if (i < C_S0)      { src = W1; off = i;          dst = wt + OFF_W1; }
    else if (i < C_S1) { src = r1; off = i - C_S0;   dst = wt + OFF_R1; }
    else if (i < C_S2) { src = W2; off = i - C_S1;   dst = wt + OFF_W2; }
    else if (i < C_S3) { src = r2; off = i - C_S2;   dst = wt + OFF_R2; }
    else if (i < C_S4) { src = m1; off = i - C_S3;   dst = wt + OFF_M1; }
    else               { src = xe; off = i - C_S4;   dst = xh; }
    float4 v = __ldg(src + off);
    __half* d = dst + (size_t)off * 4;
    ((half2*)d)[0] = __floats2half2_rn(v.x, v.y);
    ((half2*)d)[1] = __floats2half2_rn(v.z, v.w);
}

// ================= launch =================
extern "C" void kernel_launch(void* const* d_in, const int* in_sizes, int n_in,
                              void* d_out, int out_size) {
    const int*   edge_index = (const int*)d_in[0];
    const int*   etype      = (const int*)d_in[1];
    const float* etext      = (const float*)d_in[2];
    const float* node_emb   = (const float*)d_in[3];
    const float* W1         = (const float*)d_in[4];
    const float* root1      = (const float*)d_in[5];
    const float* b1         = (const float*)d_in[6];
    const float* W2         = (const float*)d_in[7];
    const float* root2      = (const float*)d_in[8];
    const float* b2         = (const float*)d_in[9];
    const float* mlpW1      = (const float*)d_in[10];
    const float* mlpb1      = (const float*)d_in[11];
    const float* mlpW2      = (const float*)d_in[12];
    const float* mlpb2      = (const float*)d_in[13];

    const int* srcv = edge_index;
    const int* dstv = edge_index + NE;
    float* logits = (float*)d_out;
    float* h2out  = (float*)d_out + NE;

    void* p;
    cudaGetSymbolAddress(&p, g_cnt);  int*    cntp = (int*)p;
    cudaGetSymbolAddress(&p, g_xWh);  __half* xWh  = (__half*)p;
    cudaGetSymbolAddress(&p, g_xh);   __half* xh   = (__half*)p;
    cudaGetSymbolAddress(&p, g_h1h);  __half* h1h  = (__half*)p;
    cudaGetSymbolAddress(&p, g_h2h);  __half* h2h  = (__half*)p;
    cudaGetSymbolAddress(&p, g_Hh);   __half* Hh   = (__half*)p;
    cudaGetSymbolAddress(&p, g_wt);   __half* wt   = (__half*)p;

    // side stream + fork/join events (created once, on the uncaptured correctness call)
    static cudaStream_t s1 = [] { cudaStream_t t; cudaStreamCreate(&t); return t; }();
    static cudaEvent_t evFork = [] { cudaEvent_t e; cudaEventCreateWithFlags(&e, cudaEventDisableTiming); return e; }();
    static cudaEvent_t evJoin = [] { cudaEvent_t e; cudaEventCreateWithFlags(&e, cudaEventDisableTiming); return e; }();

    const int GSMEM = 128 * SLD * 4;    // 67584
    const int ESMEM = 64 * 256 * 4;     // 65536
    cudaFuncSetAttribute(twmma_kernel<float>, cudaFuncAttributeMaxDynamicSharedMemorySize, GSMEM);
    cudaFuncSetAttribute(twmma_kernel<__half>, cudaFuncAttributeMaxDynamicSharedMemorySize, GSMEM);
    cudaFuncSetAttribute(edge_fused_kernel, cudaFuncAttributeMaxDynamicSharedMemorySize, ESMEM);

    // ---- fork: CSR build on side stream ----
    cudaEventRecord(evFork, 0);
    cudaStreamWaitEvent(s1, evFork, 0);
    zeroi_kernel<<<(NN * RREL + 255) / 256, 256, 0, s1>>>(cntp, NN * RREL);
    count_kernel<<<(NE + 255) / 256, 256, 0, s1>>>(dstv, etype);
    inv_deg_kernel<<<(NN + 255) / 256, 256, 0, s1>>>();
    const int NB = (NN + 1023) / 1024;   // 49
    scan1_kernel<<<NB, 1024, 0, s1>>>();
    scan2_kernel<<<1, 64, 0, s1>>>(NB);
    scan3_kernel<<<(NN + 256) / 256, 256, 0, s1>>>();
    fill_kernel<<<(NE + 255) / 256, 256, 0, s1>>>(srcv, dstv, etype);
    cudaEventRecord(evJoin, s1);

    // ---- main stream: conversions + layer-1 GEMM (independent of CSR) ----
    convert_all_kernel<<<(C_S5 + 255) / 256, 256>>>(
        (const float4*)W1, (const float4*)root1, (const float4*)W2, (const float4*)root2,
        (const float4*)mlpW1, (const float4*)node_emb, wt, xh);

    const int MB = NP / 128;  // 391
    twmma_kernel<__half><<<dim3(MB, 2, 9), 256, GSMEM>>>(xh, wt + OFF_W1, xWh,
                                                         NN, 256, 256, 256, 2304,
                                                         65536L, 256L);

    // ---- join: aggregation needs CSR ----
    cudaStreamWaitEvent(0, evJoin, 0);
    agg_kernel<256, 2304, false><<<(NN + 7) / 8, 256>>>(xWh, b1, h1h, nullptr);

    // ---- layer 2 ----
    twmma_kernel<__half><<<dim3(MB, 1, 9), 256, GSMEM>>>(h1h, wt + OFF_W2, xWh,
                                                         NN, 256, 256, 128, 1152,
                                                         32768L, 128L);
    agg_kernel<128, 1152, true><<<(NN + 15) / 16, 256>>>(xWh, b2, h2h, h2out);

    // ---- edge MLP ----
    twmma_kernel<__half><<<dim3(MB, 2, 2), 256, GSMEM>>>(h2h, wt + OFF_M1, Hh,
                                                         NN, 128, 128, 256, 256,
                                                         32768L, (long)NP * 256);
    edge_fused_kernel<<<NE / 64, 256, ESMEM>>>(srcv, dstv, etext, wt + OFF_M1 + 65536,
                                               mlpb1, mlpW2, mlpb2,
                                               Hh, Hh + (size_t)NP * 256, logits);
}